// round 3
// baseline (speedup 1.0000x reference)
#include <cuda_runtime.h>

// ---------------------------------------------------------------------------
// QThreeLayer: 6-bit quantized MLP 16 -> 64 -> 32 -> 32 -> 5, softmax.
// Integer (dp4a) emulation of the HAWQ reference. 5 sequential phases
// separated by kernel launches (global activation-max dependency).
// Scratch: q0 (16 MB) and q2 (32 MB) only; layer-1 output recomputed in K4.
// ---------------------------------------------------------------------------

#define ROWS_CAP (1 << 20)

// ---- persistent device state (reset every replay by k0_init) --------------
__device__ unsigned int g_xmax;
__device__ int g_macc1[64];
__device__ int g_macc2[32];
__device__ int g_macc3[32];

__device__ int g_W1p[64 * 4];   // packed int8x4 weights, [o][k]
__device__ int g_W2p[32 * 16];
__device__ int g_W3p[32 * 8];
__device__ int g_W4p[5 * 8];
__device__ float g_wsc1[64], g_wsc2[32], g_wsc3[32], g_wsc4[5];

__device__ float g_sf0, g_inv0;
__device__ float g_sf1, g_inv1;
__device__ float g_sf2, g_inv2;
__device__ float g_sf3, g_inv3;
__device__ float g_bsf1[64], g_bsf2[32], g_bsf3[32], g_bsf4[5];
__device__ int g_bint1[64], g_bint2[32], g_bint3[32], g_bint4[5];

// scratch: quantized activations (int8 packed in uint32 lanes)
__device__ uint4 g_q0[ROWS_CAP];        // 16 B/row
__device__ uint4 g_q2[ROWS_CAP * 2];    // 32 B/row

// ---- helpers ---------------------------------------------------------------
__device__ __forceinline__ int dp4a_(int a, int b, int c) {
    int d;
    asm("dp4a.s32.s32 %0, %1, %2, %3;" : "=r"(d) : "r"(a), "r"(b), "r"(c));
    return d;
}
__device__ __forceinline__ int iclamp(int v, int lo, int hi) {
    return v < lo ? lo : (v > hi ? hi : v);
}
__device__ __forceinline__ int pack4i(int a, int b, int c, int d) {
    return (a & 0xFF) | ((b & 0xFF) << 8) | ((c & 0xFF) << 16) | ((d & 0xFF) << 24);
}
// round(t/s) with clip to [-32,31]; fast reciprocal path + exact IEEE fallback
// when within 2e-5 of a .5 boundary (candidate error bound ~4e-6).
__device__ __forceinline__ int fquant(float t, float inv, float s) {
    float u = t * inv;
    float qa = rintf(u);
    if (0.5f - fabsf(u - qa) < 2e-5f) qa = rintf(__fdiv_rn(t, s));
    return iclamp((int)qa, -32, 31);
}

// ---- K0: reset reductions + quantize weights ------------------------------
__global__ void k0_init(const float* __restrict__ W1, const float* __restrict__ W2,
                        const float* __restrict__ W3, const float* __restrict__ W4) {
    int t = threadIdx.x;
    if (t == 0) g_xmax = 0u;
    if (t < 64) g_macc1[t] = 0;
    if (t < 32) { g_macc2[t] = 0; g_macc3[t] = 0; }

    if (t < 64) {  // layer 1: [64,16]
        const float* w = W1 + t * 16;
        float m = 0.f;
#pragma unroll
        for (int i = 0; i < 16; i++) m = fmaxf(m, fabsf(w[i]));
        float sc = __fdiv_rn(fmaxf(m, 1e-8f), 31.0f);
        g_wsc1[t] = sc;
#pragma unroll
        for (int k = 0; k < 4; k++) {
            int a = iclamp((int)rintf(__fdiv_rn(w[4 * k + 0], sc)), -32, 31);
            int b = iclamp((int)rintf(__fdiv_rn(w[4 * k + 1], sc)), -32, 31);
            int c = iclamp((int)rintf(__fdiv_rn(w[4 * k + 2], sc)), -32, 31);
            int d = iclamp((int)rintf(__fdiv_rn(w[4 * k + 3], sc)), -32, 31);
            g_W1p[t * 4 + k] = pack4i(a, b, c, d);
        }
    } else if (t < 96) {  // layer 2: [32,64]
        int o = t - 64;
        const float* w = W2 + o * 64;
        float m = 0.f;
#pragma unroll
        for (int i = 0; i < 64; i++) m = fmaxf(m, fabsf(w[i]));
        float sc = __fdiv_rn(fmaxf(m, 1e-8f), 31.0f);
        g_wsc2[o] = sc;
#pragma unroll
        for (int k = 0; k < 16; k++) {
            int a = iclamp((int)rintf(__fdiv_rn(w[4 * k + 0], sc)), -32, 31);
            int b = iclamp((int)rintf(__fdiv_rn(w[4 * k + 1], sc)), -32, 31);
            int c = iclamp((int)rintf(__fdiv_rn(w[4 * k + 2], sc)), -32, 31);
            int d = iclamp((int)rintf(__fdiv_rn(w[4 * k + 3], sc)), -32, 31);
            g_W2p[o * 16 + k] = pack4i(a, b, c, d);
        }
    } else if (t < 128) {  // layer 3: [32,32]
        int o = t - 96;
        const float* w = W3 + o * 32;
        float m = 0.f;
#pragma unroll
        for (int i = 0; i < 32; i++) m = fmaxf(m, fabsf(w[i]));
        float sc = __fdiv_rn(fmaxf(m, 1e-8f), 31.0f);
        g_wsc3[o] = sc;
#pragma unroll
        for (int k = 0; k < 8; k++) {
            int a = iclamp((int)rintf(__fdiv_rn(w[4 * k + 0], sc)), -32, 31);
            int b = iclamp((int)rintf(__fdiv_rn(w[4 * k + 1], sc)), -32, 31);
            int c = iclamp((int)rintf(__fdiv_rn(w[4 * k + 2], sc)), -32, 31);
            int d = iclamp((int)rintf(__fdiv_rn(w[4 * k + 3], sc)), -32, 31);
            g_W3p[o * 8 + k] = pack4i(a, b, c, d);
        }
    } else if (t < 133) {  // layer 4: [5,32]
        int o = t - 128;
        const float* w = W4 + o * 32;
        float m = 0.f;
#pragma unroll
        for (int i = 0; i < 32; i++) m = fmaxf(m, fabsf(w[i]));
        float sc = __fdiv_rn(fmaxf(m, 1e-8f), 31.0f);
        g_wsc4[o] = sc;
#pragma unroll
        for (int k = 0; k < 8; k++) {
            int a = iclamp((int)rintf(__fdiv_rn(w[4 * k + 0], sc)), -32, 31);
            int b = iclamp((int)rintf(__fdiv_rn(w[4 * k + 1], sc)), -32, 31);
            int c = iclamp((int)rintf(__fdiv_rn(w[4 * k + 2], sc)), -32, 31);
            int d = iclamp((int)rintf(__fdiv_rn(w[4 * k + 3], sc)), -32, 31);
            g_W4p[o * 8 + k] = pack4i(a, b, c, d);
        }
    }
}

// ---- K1: global max|x| -----------------------------------------------------
__global__ void k1_absmax(const float* __restrict__ x, int n4) {
    const float4* x4 = (const float4*)x;
    int i = blockIdx.x * blockDim.x + threadIdx.x;
    int stride = gridDim.x * blockDim.x;
    float m = 0.f;
    for (; i < n4; i += stride) {
        float4 v = x4[i];
        m = fmaxf(m, fmaxf(fmaxf(fabsf(v.x), fabsf(v.y)), fmaxf(fabsf(v.z), fabsf(v.w))));
    }
#pragma unroll
    for (int o = 16; o; o >>= 1) m = fmaxf(m, __shfl_xor_sync(0xffffffffu, m, o));
    if ((threadIdx.x & 31) == 0) atomicMax(&g_xmax, __float_as_uint(m));
}

// ---- K1b: sf0, layer-1 bias quant -----------------------------------------
__global__ void k1b_fin(const float* __restrict__ b1) {
    __shared__ float ssf;
    int t = threadIdx.x;
    if (t == 0) {
        float sf = __fdiv_rn(fmaxf(__uint_as_float(g_xmax), 1e-8f), 31.0f);
        g_sf0 = sf;
        g_inv0 = __fdiv_rn(1.0f, sf);
        ssf = sf;
    }
    __syncthreads();
    if (t < 64) {
        float bsf = __fmul_rn(g_wsc1[t], ssf);
        g_bsf1[t] = bsf;
        g_bint1[t] = iclamp((int)rintf(__fdiv_rn(b1[t], bsf)), -32, 31);
    }
}

// ---- K2: quantize x -> q0, layer-1 accum max ------------------------------
template <int RPT>
__global__ __launch_bounds__(256) void k2_l1max(const float* __restrict__ x, int rows, int nthreads) {
    __shared__ int sW[256], sb[64], smax[64];
    __shared__ float s_inv0, s_sf0;
    int t = threadIdx.x;
    sW[t] = g_W1p[t];
    if (t < 64) { sb[t] = g_bint1[t]; smax[t] = 0; }
    if (t == 0) { s_inv0 = g_inv0; s_sf0 = g_sf0; }
    __syncthreads();

    int macc[64];
#pragma unroll
    for (int o = 0; o < 64; o++) macc[o] = 0;

    int gid = blockIdx.x * blockDim.x + t;
    const float4* x4 = (const float4*)x;
    for (int r = 0; r < RPT; r++) {
        int row = gid + r * nthreads;
        if (row >= rows) break;
        int qp[4];
#pragma unroll
        for (int j = 0; j < 4; j++) {
            float4 v = x4[row * 4 + j];
            int a = fquant(v.x, s_inv0, s_sf0);
            int b = fquant(v.y, s_inv0, s_sf0);
            int c = fquant(v.z, s_inv0, s_sf0);
            int d = fquant(v.w, s_inv0, s_sf0);
            qp[j] = pack4i(a, b, c, d);
        }
        g_q0[row] = make_uint4((unsigned)qp[0], (unsigned)qp[1], (unsigned)qp[2], (unsigned)qp[3]);
#pragma unroll
        for (int o = 0; o < 64; o++) {
            int acc = sb[o];
#pragma unroll
            for (int k = 0; k < 4; k++) acc = dp4a_(qp[k], sW[o * 4 + k], acc);
            macc[o] = max(macc[o], acc);
        }
    }
#pragma unroll
    for (int o = 0; o < 64; o++) atomicMax(&smax[o], macc[o]);
    __syncthreads();
    if (t < 64) atomicMax(&g_macc1[t], smax[t]);
}

// ---- K2b: sf1, layer-2 bias quant -----------------------------------------
__global__ void k2b_fin(const float* __restrict__ b2) {
    __shared__ float red[64];
    __shared__ float s_sf;
    int t = threadIdx.x;  // 64 threads
    red[t] = __fmul_rn((float)g_macc1[t], g_bsf1[t]);
    __syncthreads();
    if (t == 0) {
        float m = red[0];
        for (int i = 1; i < 64; i++) m = fmaxf(m, red[i]);
        float sf = __fdiv_rn(fmaxf(m, 1e-8f), 31.0f);
        g_sf1 = sf;
        g_inv1 = __fdiv_rn(1.0f, sf);
        s_sf = sf;
    }
    __syncthreads();
    if (t < 32) {
        float bsf = __fmul_rn(g_wsc2[t], s_sf);
        g_bsf2[t] = bsf;
        g_bint2[t] = iclamp((int)rintf(__fdiv_rn(b2[t], bsf)), -32, 31);
    }
}

// layer1 from q0 registers -> q1 packed (16 ints). Shared weights/consts passed in.
__device__ __forceinline__ void l1_to_q1(const int qp0[4], const int* sW1, const int* sb1,
                                         const float* sbsf1, float inv1, float sf1, int q1p[16]) {
#pragma unroll
    for (int g = 0; g < 16; g++) {
        int b4[4];
#pragma unroll
        for (int j = 0; j < 4; j++) {
            int o = g * 4 + j;
            int acc = sb1[o];
#pragma unroll
            for (int k = 0; k < 4; k++) acc = dp4a_(qp0[k], sW1[o * 4 + k], acc);
            float tt = fmaxf(__fmul_rn((float)acc, sbsf1[o]), 0.f);  // relu
            b4[j] = fquant(tt, inv1, sf1);
        }
        q1p[g] = pack4i(b4[0], b4[1], b4[2], b4[3]);
    }
}

// ---- K3: q0 -> L1 -> q1 (regs) -> L2 accum max ----------------------------
template <int RPT>
__global__ __launch_bounds__(256) void k3_l2max(int rows, int nthreads) {
    __shared__ int sW1[256], sb1[64], sW2[512], sb2[32], smax[32];
    __shared__ float sbsf1[64], s_inv1, s_sf1;
    int t = threadIdx.x;
    sW1[t] = g_W1p[t];
    sW2[t] = g_W2p[t];
    sW2[t + 256] = g_W2p[t + 256];
    if (t < 64) { sb1[t] = g_bint1[t]; sbsf1[t] = g_bsf1[t]; }
    if (t < 32) { sb2[t] = g_bint2[t]; smax[t] = 0; }
    if (t == 0) { s_inv1 = g_inv1; s_sf1 = g_sf1; }
    __syncthreads();

    int macc[32];
#pragma unroll
    for (int o = 0; o < 32; o++) macc[o] = 0;

    int gid = blockIdx.x * blockDim.x + t;
    for (int r = 0; r < RPT; r++) {
        int row = gid + r * nthreads;
        if (row >= rows) break;
        uint4 qv = g_q0[row];
        int qp0[4] = {(int)qv.x, (int)qv.y, (int)qv.z, (int)qv.w};
        int q1p[16];
        l1_to_q1(qp0, sW1, sb1, sbsf1, s_inv1, s_sf1, q1p);
#pragma unroll
        for (int o = 0; o < 32; o++) {
            int acc = sb2[o];
#pragma unroll
            for (int k = 0; k < 16; k++) acc = dp4a_(q1p[k], sW2[o * 16 + k], acc);
            macc[o] = max(macc[o], acc);
        }
    }
#pragma unroll
    for (int o = 0; o < 32; o++) atomicMax(&smax[o], macc[o]);
    __syncthreads();
    if (t < 32) atomicMax(&g_macc2[t], smax[t]);
}

// ---- K3b: sf2, layer-3 bias quant -----------------------------------------
__global__ void k3b_fin(const float* __restrict__ b3) {
    __shared__ float red[32];
    __shared__ float s_sf;
    int t = threadIdx.x;  // 32 threads
    red[t] = __fmul_rn((float)g_macc2[t], g_bsf2[t]);
    __syncthreads();
    if (t == 0) {
        float m = red[0];
        for (int i = 1; i < 32; i++) m = fmaxf(m, red[i]);
        float sf = __fdiv_rn(fmaxf(m, 1e-8f), 31.0f);
        g_sf2 = sf;
        g_inv2 = __fdiv_rn(1.0f, sf);
        s_sf = sf;
    }
    __syncthreads();
    if (t < 32) {
        float bsf = __fmul_rn(g_wsc3[t], s_sf);
        g_bsf3[t] = bsf;
        g_bint3[t] = iclamp((int)rintf(__fdiv_rn(b3[t], bsf)), -32, 31);
    }
}

// ---- K4: q0 -> L1 -> q1 (regs) -> L2 -> q2 store -> L3 accum max ----------
template <int RPT>
__global__ __launch_bounds__(256) void k4_l3max(int rows, int nthreads) {
    __shared__ int sW1[256], sb1[64], sW2[512], sb2[32], sW3[256], sb3[32], smax[32];
    __shared__ float sbsf1[64], sbsf2[32], s_inv1, s_sf1, s_inv2, s_sf2;
    int t = threadIdx.x;
    sW1[t] = g_W1p[t];
    sW2[t] = g_W2p[t];
    sW2[t + 256] = g_W2p[t + 256];
    sW3[t] = g_W3p[t];
    if (t < 64) { sb1[t] = g_bint1[t]; sbsf1[t] = g_bsf1[t]; }
    if (t < 32) { sb2[t] = g_bint2[t]; sbsf2[t] = g_bsf2[t]; sb3[t] = g_bint3[t]; smax[t] = 0; }
    if (t == 0) { s_inv1 = g_inv1; s_sf1 = g_sf1; s_inv2 = g_inv2; s_sf2 = g_sf2; }
    __syncthreads();

    int macc[32];
#pragma unroll
    for (int o = 0; o < 32; o++) macc[o] = 0;

    int gid = blockIdx.x * blockDim.x + t;
    for (int r = 0; r < RPT; r++) {
        int row = gid + r * nthreads;
        if (row >= rows) break;
        uint4 qv = g_q0[row];
        int qp0[4] = {(int)qv.x, (int)qv.y, (int)qv.z, (int)qv.w};
        int q1p[16];
        l1_to_q1(qp0, sW1, sb1, sbsf1, s_inv1, s_sf1, q1p);
        int q2p[8];
#pragma unroll
        for (int g = 0; g < 8; g++) {
            int b4[4];
#pragma unroll
            for (int j = 0; j < 4; j++) {
                int o = g * 4 + j;
                int acc = sb2[o];
#pragma unroll
                for (int k = 0; k < 16; k++) acc = dp4a_(q1p[k], sW2[o * 16 + k], acc);
                float tt = fmaxf(__fmul_rn((float)acc, sbsf2[o]), 0.f);
                b4[j] = fquant(tt, s_inv2, s_sf2);
            }
            q2p[g] = pack4i(b4[0], b4[1], b4[2], b4[3]);
        }
        uint4* q2o = &g_q2[row * 2];
        q2o[0] = make_uint4((unsigned)q2p[0], (unsigned)q2p[1], (unsigned)q2p[2], (unsigned)q2p[3]);
        q2o[1] = make_uint4((unsigned)q2p[4], (unsigned)q2p[5], (unsigned)q2p[6], (unsigned)q2p[7]);
#pragma unroll
        for (int o = 0; o < 32; o++) {
            int acc = sb3[o];
#pragma unroll
            for (int k = 0; k < 8; k++) acc = dp4a_(q2p[k], sW3[o * 8 + k], acc);
            macc[o] = max(macc[o], acc);
        }
    }
#pragma unroll
    for (int o = 0; o < 32; o++) atomicMax(&smax[o], macc[o]);
    __syncthreads();
    if (t < 32) atomicMax(&g_macc3[t], smax[t]);
}

// ---- K4b: sf3, layer-4 bias quant -----------------------------------------
__global__ void k4b_fin(const float* __restrict__ b4) {
    __shared__ float red[32];
    __shared__ float s_sf;
    int t = threadIdx.x;  // 32 threads
    red[t] = __fmul_rn((float)g_macc3[t], g_bsf3[t]);
    __syncthreads();
    if (t == 0) {
        float m = red[0];
        for (int i = 1; i < 32; i++) m = fmaxf(m, red[i]);
        float sf = __fdiv_rn(fmaxf(m, 1e-8f), 31.0f);
        g_sf3 = sf;
        g_inv3 = __fdiv_rn(1.0f, sf);
        s_sf = sf;
    }
    __syncthreads();
    if (t < 5) {
        float bsf = __fmul_rn(g_wsc4[t], s_sf);
        g_bsf4[t] = bsf;
        g_bint4[t] = iclamp((int)rintf(__fdiv_rn(b4[t], bsf)), -32, 31);
    }
}

// ---- K5: q2 -> L3, quant q3, L4, softmax, store ---------------------------
template <int RPT>
__global__ __launch_bounds__(256) void k5_out(float* __restrict__ out, int rows, int nthreads) {
    __shared__ int sW3[256], sb3[32], sW4[40], sb4[5];
    __shared__ float sbsf3[32], sbsf4[5], s_inv3, s_sf3;
    int t = threadIdx.x;
    sW3[t] = g_W3p[t];
    if (t < 40) sW4[t] = g_W4p[t];
    if (t < 32) { sb3[t] = g_bint3[t]; sbsf3[t] = g_bsf3[t]; }
    if (t < 5) { sb4[t] = g_bint4[t]; sbsf4[t] = g_bsf4[t]; }
    if (t == 0) { s_inv3 = g_inv3; s_sf3 = g_sf3; }
    __syncthreads();

    int gid = blockIdx.x * blockDim.x + t;
    for (int r = 0; r < RPT; r++) {
        int row = gid + r * nthreads;
        if (row >= rows) break;
        const uint4* q2i = &g_q2[row * 2];
        uint4 v0 = q2i[0], v1 = q2i[1];
        int q2p[8] = {(int)v0.x, (int)v0.y, (int)v0.z, (int)v0.w,
                      (int)v1.x, (int)v1.y, (int)v1.z, (int)v1.w};
        int q3p[8];
#pragma unroll
        for (int g = 0; g < 8; g++) {
            int b4v[4];
#pragma unroll
            for (int j = 0; j < 4; j++) {
                int o = g * 4 + j;
                int acc = sb3[o];
#pragma unroll
                for (int k = 0; k < 8; k++) acc = dp4a_(q2p[k], sW3[o * 8 + k], acc);
                float tt = fmaxf(__fmul_rn((float)acc, sbsf3[o]), 0.f);
                b4v[j] = fquant(tt, s_inv3, s_sf3);
            }
            q3p[g] = pack4i(b4v[0], b4v[1], b4v[2], b4v[3]);
        }
        float logit[5];
#pragma unroll
        for (int c = 0; c < 5; c++) {
            int acc = sb4[c];
#pragma unroll
            for (int k = 0; k < 8; k++) acc = dp4a_(q3p[k], sW4[c * 8 + k], acc);
            logit[c] = __fmul_rn((float)acc, sbsf4[c]);
        }
        float m = logit[0];
#pragma unroll
        for (int c = 1; c < 5; c++) m = fmaxf(m, logit[c]);
        float e[5], s = 0.f;
#pragma unroll
        for (int c = 0; c < 5; c++) { e[c] = __expf(logit[c] - m); s += e[c]; }
        float rs = __frcp_rn(s);
        float* po = out + (long long)row * 5;
#pragma unroll
        for (int c = 0; c < 5; c++) po[c] = e[c] * rs;
    }
}

// ---- launcher --------------------------------------------------------------
extern "C" void kernel_launch(void* const* d_in, const int* in_sizes, int n_in,
                              void* d_out, int out_size) {
    const float* x  = (const float*)d_in[0];
    const float* W1 = (const float*)d_in[1];
    const float* b1 = (const float*)d_in[2];
    const float* W2 = (const float*)d_in[3];
    const float* b2 = (const float*)d_in[4];
    const float* W3 = (const float*)d_in[5];
    const float* b3 = (const float*)d_in[6];
    const float* W4 = (const float*)d_in[7];
    const float* b4 = (const float*)d_in[8];
    float* out = (float*)d_out;

    int rows = in_sizes[0] / 16;
    if (rows > ROWS_CAP) rows = ROWS_CAP;

    k0_init<<<1, 256>>>(W1, W2, W3, W4);
    k1_absmax<<<1024, 256>>>(x, rows * 4);
    k1b_fin<<<1, 64>>>(b1);

    {
        constexpr int RPT = 8;
        int nth = (rows + RPT - 1) / RPT;
        int grid = (nth + 255) / 256;
        nth = grid * 256;
        k2_l1max<RPT><<<grid, 256>>>(x, rows, nth);
    }
    k2b_fin<<<1, 64>>>(b2);
    {
        constexpr int RPT = 8;
        int nth = (rows + RPT - 1) / RPT;
        int grid = (nth + 255) / 256;
        nth = grid * 256;
        k3_l2max<RPT><<<grid, 256>>>(rows, nth);
    }
    k3b_fin<<<1, 32>>>(b3);
    {
        constexpr int RPT = 8;
        int nth = (rows + RPT - 1) / RPT;
        int grid = (nth + 255) / 256;
        nth = grid * 256;
        k4_l3max<RPT><<<grid, 256>>>(rows, nth);
    }
    k4b_fin<<<1, 32>>>(b4);
    {
        constexpr int RPT = 4;
        int nth = (rows + RPT - 1) / RPT;
        int grid = (nth + 255) / 256;
        nth = grid * 256;
        k5_out<RPT><<<grid, 256>>>(out, rows, nth);
    }
    (void)n_in; (void)out_size;
}

// round 4
// speedup vs baseline: 2.3902x; 2.3902x over previous
#include <cuda_runtime.h>
#include <cstdint>

// ---------------------------------------------------------------------------
// QThreeLayer: 6-bit quantized MLP 16 -> 64 -> 32 -> 32 -> 5, softmax.
// dp4a integer emulation, each layer computed EXACTLY once.
// Inter-phase state: raw integer accumulators (acc1 i16, acc2 i32, acc3 i16).
// ---------------------------------------------------------------------------

#define ROWS_CAP (1 << 20)

// ---- persistent device state (reset every replay by k0_init) --------------
__device__ unsigned int g_xmax;
__device__ int g_macc1[64], g_macc2[32], g_macc3[32];

__device__ int g_W1p[64 * 4];   // packed int8x4 weights, [o][k]
__device__ int g_W2p[32 * 16];
__device__ int g_W3p[32 * 8];
__device__ int g_W4p[5 * 8];
__device__ float g_wsc1[64], g_wsc2[32], g_wsc3[32], g_wsc4[5];

__device__ float g_sf0, g_inv0;
__device__ float g_sf1, g_sf2, g_sf3;
__device__ float g_bsf1[64], g_bsf2[32], g_bsf3[32], g_bsf4[5];
__device__ float g_cmb1[64], g_cmb2[32], g_cmb3[32];  // bsf/sf combined
__device__ int g_bint1[64], g_bint2[32], g_bint3[32], g_bint4[5];

// inter-phase accumulators
__device__ uint4 g_a1[ROWS_CAP * 8];  // L1 accs int16, 128 B/row
__device__ uint4 g_a2[ROWS_CAP * 8];  // L2 accs int32, 128 B/row
__device__ uint4 g_a3[ROWS_CAP * 4];  // L3 accs int16,  64 B/row

// ---- helpers ---------------------------------------------------------------
__device__ __forceinline__ int dp4a_(int a, int b, int c) {
    int d;
    asm("dp4a.s32.s32 %0, %1, %2, %3;" : "=r"(d) : "r"(a), "r"(b), "r"(c));
    return d;
}
__device__ __forceinline__ int iclamp(int v, int lo, int hi) {
    return v < lo ? lo : (v > hi ? hi : v);
}
__device__ __forceinline__ int pack4i(int a, int b, int c, int d) {
    return (a & 0xFF) | ((b & 0xFF) << 8) | ((c & 0xFF) << 16) | ((d & 0xFF) << 24);
}
__device__ __forceinline__ int lo16(unsigned u) { return (int)(u << 16) >> 16; }
__device__ __forceinline__ int hi16(unsigned u) { return (int)u >> 16; }

// round(t/s) with clip to [-32,31]; reciprocal fast path + exact IEEE
// fallback near .5 boundaries.
__device__ __forceinline__ int fquant(float t, float inv, float s) {
    float u = t * inv;
    float qa = rintf(u);
    if (0.5f - fabsf(u - qa) < 2e-5f) qa = rintf(__fdiv_rn(t, s));
    return iclamp((int)qa, -32, 31);
}

// quantize relu(acc*bsf)/sf where cmb = bsf/sf precomputed; result in [0,31]
__device__ __forceinline__ int fquant_pos(float accf, float cmb, float bsf, float sf) {
    float u = fmaxf(accf * cmb, 0.f);
    float qa = rintf(u);
    if (0.5f - fabsf(u - qa) < 2e-5f) {
        float h = fmaxf(__fmul_rn(accf, bsf), 0.f);
        qa = rintf(__fdiv_rn(h, sf));
    }
    int q = (int)qa;
    return q > 31 ? 31 : q;
}

// quantize 4 int16-acc channels (from two packed uints) into one int8x4 word
__device__ __forceinline__ int quant4_i16(unsigned u0, unsigned u1, int ob,
                                          const float* cmb, const float* bsf, float sf) {
    int a = fquant_pos((float)lo16(u0), cmb[ob + 0], bsf[ob + 0], sf);
    int b = fquant_pos((float)hi16(u0), cmb[ob + 1], bsf[ob + 1], sf);
    int c = fquant_pos((float)lo16(u1), cmb[ob + 2], bsf[ob + 2], sf);
    int d = fquant_pos((float)hi16(u1), cmb[ob + 3], bsf[ob + 3], sf);
    return pack4i(a, b, c, d);
}

// ---- K0: reset reductions + quantize weights ------------------------------
__global__ void k0_init(const float* __restrict__ W1, const float* __restrict__ W2,
                        const float* __restrict__ W3, const float* __restrict__ W4) {
    int t = threadIdx.x;
    if (t == 0) g_xmax = 0u;
    if (t < 64) g_macc1[t] = 0;
    if (t < 32) { g_macc2[t] = 0; g_macc3[t] = 0; }

    if (t < 64) {  // layer 1: [64,16]
        const float* w = W1 + t * 16;
        float m = 0.f;
#pragma unroll
        for (int i = 0; i < 16; i++) m = fmaxf(m, fabsf(w[i]));
        float sc = __fdiv_rn(fmaxf(m, 1e-8f), 31.0f);
        g_wsc1[t] = sc;
#pragma unroll
        for (int k = 0; k < 4; k++) {
            int a = iclamp((int)rintf(__fdiv_rn(w[4 * k + 0], sc)), -32, 31);
            int b = iclamp((int)rintf(__fdiv_rn(w[4 * k + 1], sc)), -32, 31);
            int c = iclamp((int)rintf(__fdiv_rn(w[4 * k + 2], sc)), -32, 31);
            int d = iclamp((int)rintf(__fdiv_rn(w[4 * k + 3], sc)), -32, 31);
            g_W1p[t * 4 + k] = pack4i(a, b, c, d);
        }
    } else if (t < 96) {  // layer 2: [32,64]
        int o = t - 64;
        const float* w = W2 + o * 64;
        float m = 0.f;
#pragma unroll
        for (int i = 0; i < 64; i++) m = fmaxf(m, fabsf(w[i]));
        float sc = __fdiv_rn(fmaxf(m, 1e-8f), 31.0f);
        g_wsc2[o] = sc;
#pragma unroll
        for (int k = 0; k < 16; k++) {
            int a = iclamp((int)rintf(__fdiv_rn(w[4 * k + 0], sc)), -32, 31);
            int b = iclamp((int)rintf(__fdiv_rn(w[4 * k + 1], sc)), -32, 31);
            int c = iclamp((int)rintf(__fdiv_rn(w[4 * k + 2], sc)), -32, 31);
            int d = iclamp((int)rintf(__fdiv_rn(w[4 * k + 3], sc)), -32, 31);
            g_W2p[o * 16 + k] = pack4i(a, b, c, d);
        }
    } else if (t < 128) {  // layer 3: [32,32]
        int o = t - 96;
        const float* w = W3 + o * 32;
        float m = 0.f;
#pragma unroll
        for (int i = 0; i < 32; i++) m = fmaxf(m, fabsf(w[i]));
        float sc = __fdiv_rn(fmaxf(m, 1e-8f), 31.0f);
        g_wsc3[o] = sc;
#pragma unroll
        for (int k = 0; k < 8; k++) {
            int a = iclamp((int)rintf(__fdiv_rn(w[4 * k + 0], sc)), -32, 31);
            int b = iclamp((int)rintf(__fdiv_rn(w[4 * k + 1], sc)), -32, 31);
            int c = iclamp((int)rintf(__fdiv_rn(w[4 * k + 2], sc)), -32, 31);
            int d = iclamp((int)rintf(__fdiv_rn(w[4 * k + 3], sc)), -32, 31);
            g_W3p[o * 8 + k] = pack4i(a, b, c, d);
        }
    } else if (t < 133) {  // layer 4: [5,32]
        int o = t - 128;
        const float* w = W4 + o * 32;
        float m = 0.f;
#pragma unroll
        for (int i = 0; i < 32; i++) m = fmaxf(m, fabsf(w[i]));
        float sc = __fdiv_rn(fmaxf(m, 1e-8f), 31.0f);
        g_wsc4[o] = sc;
#pragma unroll
        for (int k = 0; k < 8; k++) {
            int a = iclamp((int)rintf(__fdiv_rn(w[4 * k + 0], sc)), -32, 31);
            int b = iclamp((int)rintf(__fdiv_rn(w[4 * k + 1], sc)), -32, 31);
            int c = iclamp((int)rintf(__fdiv_rn(w[4 * k + 2], sc)), -32, 31);
            int d = iclamp((int)rintf(__fdiv_rn(w[4 * k + 3], sc)), -32, 31);
            g_W4p[o * 8 + k] = pack4i(a, b, c, d);
        }
    }
}

// ---- K1: global max|x| -----------------------------------------------------
__global__ void k1_absmax(const float* __restrict__ x, int n4) {
    const float4* x4 = (const float4*)x;
    int i = blockIdx.x * blockDim.x + threadIdx.x;
    int stride = gridDim.x * blockDim.x;
    float m = 0.f;
    for (; i < n4; i += stride) {
        float4 v = x4[i];
        m = fmaxf(m, fmaxf(fmaxf(fabsf(v.x), fabsf(v.y)), fmaxf(fabsf(v.z), fabsf(v.w))));
    }
#pragma unroll
    for (int o = 16; o; o >>= 1) m = fmaxf(m, __shfl_xor_sync(0xffffffffu, m, o));
    if ((threadIdx.x & 31) == 0) atomicMax(&g_xmax, __float_as_uint(m));
}

// ---- K1b: sf0, layer-1 bias quant -----------------------------------------
__global__ void k1b_fin(const float* __restrict__ b1) {
    __shared__ float ssf;
    int t = threadIdx.x;
    if (t == 0) {
        float sf = __fdiv_rn(fmaxf(__uint_as_float(g_xmax), 1e-8f), 31.0f);
        g_sf0 = sf;
        g_inv0 = __fdiv_rn(1.0f, sf);
        ssf = sf;
    }
    __syncthreads();
    if (t < 64) {
        float bsf = __fmul_rn(g_wsc1[t], ssf);
        g_bsf1[t] = bsf;
        g_bint1[t] = iclamp((int)rintf(__fdiv_rn(b1[t], bsf)), -32, 31);
    }
}

// ---- K2: x -> q0 (regs) -> L1, store acc1 i16, per-channel max ------------
__global__ __launch_bounds__(256) void k2_l1(const float* __restrict__ x,
                                             int rows, int npair, int nt) {
    __shared__ int sW[256], sb[64], smaxS[64];
    __shared__ float sc0[2];
    int t = threadIdx.x;
    sW[t] = g_W1p[t];
    if (t < 64) { sb[t] = g_bint1[t]; smaxS[t] = 0; }
    if (t == 0) { sc0[0] = g_inv0; sc0[1] = g_sf0; }
    __syncthreads();
    float inv0 = sc0[0], sf0 = sc0[1];

    int macc[64];
#pragma unroll
    for (int o = 0; o < 64; o++) macc[o] = 0;

    int gid = blockIdx.x * 256 + t;
    const float4* x4 = (const float4*)x;
#pragma unroll 1
    for (int p = gid; p < npair; p += nt) {
        int rA = p, rB = p + npair;
        bool hB = rB < rows;
        int qa[4], qb[4] = {0, 0, 0, 0};
#pragma unroll
        for (int j = 0; j < 4; j++) {
            float4 v = x4[(size_t)rA * 4 + j];
            qa[j] = pack4i(fquant(v.x, inv0, sf0), fquant(v.y, inv0, sf0),
                           fquant(v.z, inv0, sf0), fquant(v.w, inv0, sf0));
        }
        if (hB) {
#pragma unroll
            for (int j = 0; j < 4; j++) {
                float4 v = x4[(size_t)rB * 4 + j];
                qb[j] = pack4i(fquant(v.x, inv0, sf0), fquant(v.y, inv0, sf0),
                               fquant(v.z, inv0, sf0), fquant(v.w, inv0, sf0));
            }
        }
        uint4* pA = g_a1 + (size_t)rA * 8;
        uint4* pB = g_a1 + (size_t)rB * 8;
#pragma unroll
        for (int og = 0; og < 8; og++) {
            unsigned wA[4], wB[4];
#pragma unroll
            for (int j = 0; j < 4; j++) {
                int o0 = og * 8 + 2 * j, o1 = o0 + 1;
                int aA0 = sb[o0], aA1 = sb[o1], aB0 = sb[o0], aB1 = sb[o1];
#pragma unroll
                for (int k = 0; k < 4; k++) {
                    int w0 = sW[o0 * 4 + k], w1 = sW[o1 * 4 + k];
                    aA0 = dp4a_(qa[k], w0, aA0);
                    aA1 = dp4a_(qa[k], w1, aA1);
                    aB0 = dp4a_(qb[k], w0, aB0);
                    aB1 = dp4a_(qb[k], w1, aB1);
                }
                int m0 = aA0, m1 = aA1;
                if (hB) { m0 = max(m0, aB0); m1 = max(m1, aB1); }
                macc[o0] = max(macc[o0], m0);
                macc[o1] = max(macc[o1], m1);
                wA[j] = ((unsigned)aA0 & 0xFFFFu) | ((unsigned)aA1 << 16);
                wB[j] = ((unsigned)aB0 & 0xFFFFu) | ((unsigned)aB1 << 16);
            }
            pA[og] = make_uint4(wA[0], wA[1], wA[2], wA[3]);
            if (hB) pB[og] = make_uint4(wB[0], wB[1], wB[2], wB[3]);
        }
    }
    int lane = t & 31;
#pragma unroll
    for (int o = 0; o < 64; o++) {
        int m = macc[o];
#pragma unroll
        for (int s = 16; s; s >>= 1) m = max(m, __shfl_xor_sync(0xffffffffu, m, s));
        if (lane == 0) atomicMax(&smaxS[o], m);
    }
    __syncthreads();
    if (t < 64) atomicMax(&g_macc1[t], smaxS[t]);
}

// ---- K2b: sf1, cmb1, layer-2 bias quant -----------------------------------
__global__ void k2b_fin(const float* __restrict__ b2) {
    __shared__ float red[64];
    __shared__ float s_sf, s_inv;
    int t = threadIdx.x;  // 64 threads
    red[t] = __fmul_rn((float)g_macc1[t], g_bsf1[t]);
    __syncthreads();
    if (t == 0) {
        float m = red[0];
        for (int i = 1; i < 64; i++) m = fmaxf(m, red[i]);
        float sf = __fdiv_rn(fmaxf(m, 1e-8f), 31.0f);
        g_sf1 = sf;
        s_sf = sf;
        s_inv = __fdiv_rn(1.0f, sf);
    }
    __syncthreads();
    g_cmb1[t] = __fmul_rn(g_bsf1[t], s_inv);
    if (t < 32) {
        float bsf = __fmul_rn(g_wsc2[t], s_sf);
        g_bsf2[t] = bsf;
        g_bint2[t] = iclamp((int)rintf(__fdiv_rn(b2[t], bsf)), -32, 31);
    }
}

// ---- K3: acc1 -> q1 -> L2, store acc2 i32, per-channel max ----------------
__global__ __launch_bounds__(256) void k3_l2(int rows, int npair, int nt) {
    __shared__ int sW2[512], sb2[32], smaxS[32];
    __shared__ float scmb1[64], sbsf1[64], scc[1];
    int t = threadIdx.x;
    sW2[t] = g_W2p[t];
    sW2[t + 256] = g_W2p[t + 256];
    if (t < 64) { scmb1[t] = g_cmb1[t]; sbsf1[t] = g_bsf1[t]; }
    if (t < 32) { sb2[t] = g_bint2[t]; smaxS[t] = 0; }
    if (t == 0) scc[0] = g_sf1;
    __syncthreads();
    float sf1 = scc[0];

    int macc[32];
#pragma unroll
    for (int o = 0; o < 32; o++) macc[o] = 0;

    int gid = blockIdx.x * 256 + t;
#pragma unroll 1
    for (int p = gid; p < npair; p += nt) {
        int rA = p, rB = p + npair;
        bool hB = rB < rows;
        int q1A[16], q1B[16];
        const uint4* pa = g_a1 + (size_t)rA * 8;
#pragma unroll
        for (int c = 0; c < 8; c++) {
            uint4 v = pa[c];
            q1A[c * 2 + 0] = quant4_i16(v.x, v.y, c * 8 + 0, scmb1, sbsf1, sf1);
            q1A[c * 2 + 1] = quant4_i16(v.z, v.w, c * 8 + 4, scmb1, sbsf1, sf1);
        }
        if (hB) {
            const uint4* pb = g_a1 + (size_t)rB * 8;
#pragma unroll
            for (int c = 0; c < 8; c++) {
                uint4 v = pb[c];
                q1B[c * 2 + 0] = quant4_i16(v.x, v.y, c * 8 + 0, scmb1, sbsf1, sf1);
                q1B[c * 2 + 1] = quant4_i16(v.z, v.w, c * 8 + 4, scmb1, sbsf1, sf1);
            }
        } else {
#pragma unroll
            for (int k = 0; k < 16; k++) q1B[k] = 0;
        }
        uint4* oA = g_a2 + (size_t)rA * 8;
        uint4* oB = g_a2 + (size_t)rB * 8;
#pragma unroll
        for (int og = 0; og < 8; og++) {
            int wndA[4], wndB[4];
#pragma unroll
            for (int j = 0; j < 4; j++) {
                int o = og * 4 + j;
                int aA = sb2[o], aB = sb2[o];
#pragma unroll
                for (int k = 0; k < 16; k++) {
                    int w = sW2[o * 16 + k];
                    aA = dp4a_(q1A[k], w, aA);
                    aB = dp4a_(q1B[k], w, aB);
                }
                int m = aA;
                if (hB) m = max(m, aB);
                macc[o] = max(macc[o], m);
                wndA[j] = aA;
                wndB[j] = aB;
            }
            oA[og] = make_uint4((unsigned)wndA[0], (unsigned)wndA[1],
                                (unsigned)wndA[2], (unsigned)wndA[3]);
            if (hB) oB[og] = make_uint4((unsigned)wndB[0], (unsigned)wndB[1],
                                        (unsigned)wndB[2], (unsigned)wndB[3]);
        }
    }
    int lane = t & 31;
#pragma unroll
    for (int o = 0; o < 32; o++) {
        int m = macc[o];
#pragma unroll
        for (int s = 16; s; s >>= 1) m = max(m, __shfl_xor_sync(0xffffffffu, m, s));
        if (lane == 0) atomicMax(&smaxS[o], m);
    }
    __syncthreads();
    if (t < 32) atomicMax(&g_macc2[t], smaxS[t]);
}

// ---- K3b: sf2, cmb2, layer-3 bias quant -----------------------------------
__global__ void k3b_fin(const float* __restrict__ b3) {
    __shared__ float red[32];
    __shared__ float s_sf, s_inv;
    int t = threadIdx.x;  // 32 threads
    red[t] = __fmul_rn((float)g_macc2[t], g_bsf2[t]);
    __syncthreads();
    if (t == 0) {
        float m = red[0];
        for (int i = 1; i < 32; i++) m = fmaxf(m, red[i]);
        float sf = __fdiv_rn(fmaxf(m, 1e-8f), 31.0f);
        g_sf2 = sf;
        s_sf = sf;
        s_inv = __fdiv_rn(1.0f, sf);
    }
    __syncthreads();
    g_cmb2[t] = __fmul_rn(g_bsf2[t], s_inv);
    {
        float bsf = __fmul_rn(g_wsc3[t], s_sf);
        g_bsf3[t] = bsf;
        g_bint3[t] = iclamp((int)rintf(__fdiv_rn(b3[t], bsf)), -32, 31);
    }
}

// ---- K4: acc2 -> q2 -> L3, store acc3 i16, per-channel max ----------------
__global__ __launch_bounds__(256) void k4_l3(int rows, int npair, int nt) {
    __shared__ int sW3[256], sb3[32], smaxS[32];
    __shared__ float scmb2[32], sbsf2[32], scc[1];
    int t = threadIdx.x;
    sW3[t] = g_W3p[t];
    if (t < 32) {
        scmb2[t] = g_cmb2[t];
        sbsf2[t] = g_bsf2[t];
        sb3[t] = g_bint3[t];
        smaxS[t] = 0;
    }
    if (t == 0) scc[0] = g_sf2;
    __syncthreads();
    float sf2 = scc[0];

    int macc[32];
#pragma unroll
    for (int o = 0; o < 32; o++) macc[o] = 0;

    int gid = blockIdx.x * 256 + t;
#pragma unroll 1
    for (int p = gid; p < npair; p += nt) {
        int rA = p, rB = p + npair;
        bool hB = rB < rows;
        int q2A[8], q2B[8];
        const uint4* pa = g_a2 + (size_t)rA * 8;
#pragma unroll
        for (int c = 0; c < 2; c++) {  // 4 uint4 pairs -> 8 words
            uint4 v0 = pa[c * 4 + 0], v1 = pa[c * 4 + 1], v2 = pa[c * 4 + 2], v3 = pa[c * 4 + 3];
            int ob = c * 16;
            q2A[c * 4 + 0] = pack4i(
                fquant_pos((float)(int)v0.x, scmb2[ob + 0], sbsf2[ob + 0], sf2),
                fquant_pos((float)(int)v0.y, scmb2[ob + 1], sbsf2[ob + 1], sf2),
                fquant_pos((float)(int)v0.z, scmb2[ob + 2], sbsf2[ob + 2], sf2),
                fquant_pos((float)(int)v0.w, scmb2[ob + 3], sbsf2[ob + 3], sf2));
            q2A[c * 4 + 1] = pack4i(
                fquant_pos((float)(int)v1.x, scmb2[ob + 4], sbsf2[ob + 4], sf2),
                fquant_pos((float)(int)v1.y, scmb2[ob + 5], sbsf2[ob + 5], sf2),
                fquant_pos((float)(int)v1.z, scmb2[ob + 6], sbsf2[ob + 6], sf2),
                fquant_pos((float)(int)v1.w, scmb2[ob + 7], sbsf2[ob + 7], sf2));
            q2A[c * 4 + 2] = pack4i(
                fquant_pos((float)(int)v2.x, scmb2[ob + 8], sbsf2[ob + 8], sf2),
                fquant_pos((float)(int)v2.y, scmb2[ob + 9], sbsf2[ob + 9], sf2),
                fquant_pos((float)(int)v2.z, scmb2[ob + 10], sbsf2[ob + 10], sf2),
                fquant_pos((float)(int)v2.w, scmb2[ob + 11], sbsf2[ob + 11], sf2));
            q2A[c * 4 + 3] = pack4i(
                fquant_pos((float)(int)v3.x, scmb2[ob + 12], sbsf2[ob + 12], sf2),
                fquant_pos((float)(int)v3.y, scmb2[ob + 13], sbsf2[ob + 13], sf2),
                fquant_pos((float)(int)v3.z, scmb2[ob + 14], sbsf2[ob + 14], sf2),
                fquant_pos((float)(int)v3.w, scmb2[ob + 15], sbsf2[ob + 15], sf2));
        }
        if (hB) {
            const uint4* pb = g_a2 + (size_t)rB * 8;
#pragma unroll
            for (int c = 0; c < 8; c++) {
                uint4 v = pb[c];
                int ob = c * 4;
                q2B[c] = pack4i(
                    fquant_pos((float)(int)v.x, scmb2[ob + 0], sbsf2[ob + 0], sf2),
                    fquant_pos((float)(int)v.y, scmb2[ob + 1], sbsf2[ob + 1], sf2),
                    fquant_pos((float)(int)v.z, scmb2[ob + 2], sbsf2[ob + 2], sf2),
                    fquant_pos((float)(int)v.w, scmb2[ob + 3], sbsf2[ob + 3], sf2));
            }
        } else {
#pragma unroll
            for (int k = 0; k < 8; k++) q2B[k] = 0;
        }
        uint4* oA = g_a3 + (size_t)rA * 4;
        uint4* oB = g_a3 + (size_t)rB * 4;
#pragma unroll
        for (int og = 0; og < 4; og++) {  // 8 outs per group -> one uint4 of shorts
            unsigned wA[4], wB[4];
#pragma unroll
            for (int j = 0; j < 4; j++) {
                int o0 = og * 8 + 2 * j, o1 = o0 + 1;
                int aA0 = sb3[o0], aA1 = sb3[o1], aB0 = sb3[o0], aB1 = sb3[o1];
#pragma unroll
                for (int k = 0; k < 8; k++) {
                    int w0 = sW3[o0 * 8 + k], w1 = sW3[o1 * 8 + k];
                    aA0 = dp4a_(q2A[k], w0, aA0);
                    aA1 = dp4a_(q2A[k], w1, aA1);
                    aB0 = dp4a_(q2B[k], w0, aB0);
                    aB1 = dp4a_(q2B[k], w1, aB1);
                }
                int m0 = aA0, m1 = aA1;
                if (hB) { m0 = max(m0, aB0); m1 = max(m1, aB1); }
                macc[o0] = max(macc[o0], m0);
                macc[o1] = max(macc[o1], m1);
                wA[j] = ((unsigned)aA0 & 0xFFFFu) | ((unsigned)aA1 << 16);
                wB[j] = ((unsigned)aB0 & 0xFFFFu) | ((unsigned)aB1 << 16);
            }
            oA[og] = make_uint4(wA[0], wA[1], wA[2], wA[3]);
            if (hB) oB[og] = make_uint4(wB[0], wB[1], wB[2], wB[3]);
        }
    }
    int lane = t & 31;
#pragma unroll
    for (int o = 0; o < 32; o++) {
        int m = macc[o];
#pragma unroll
        for (int s = 16; s; s >>= 1) m = max(m, __shfl_xor_sync(0xffffffffu, m, s));
        if (lane == 0) atomicMax(&smaxS[o], m);
    }
    __syncthreads();
    if (t < 32) atomicMax(&g_macc3[t], smaxS[t]);
}

// ---- K4b: sf3, cmb3, layer-4 bias quant -----------------------------------
__global__ void k4b_fin(const float* __restrict__ b4) {
    __shared__ float red[32];
    __shared__ float s_sf, s_inv;
    int t = threadIdx.x;  // 32 threads
    red[t] = __fmul_rn((float)g_macc3[t], g_bsf3[t]);
    __syncthreads();
    if (t == 0) {
        float m = red[0];
        for (int i = 1; i < 32; i++) m = fmaxf(m, red[i]);
        float sf = __fdiv_rn(fmaxf(m, 1e-8f), 31.0f);
        g_sf3 = sf;
        s_sf = sf;
        s_inv = __fdiv_rn(1.0f, sf);
    }
    __syncthreads();
    g_cmb3[t] = __fmul_rn(g_bsf3[t], s_inv);
    if (t < 5) {
        float bsf = __fmul_rn(g_wsc4[t], s_sf);
        g_bsf4[t] = bsf;
        g_bint4[t] = iclamp((int)rintf(__fdiv_rn(b4[t], bsf)), -32, 31);
    }
}

// ---- K5: acc3 -> q3 -> L4, softmax, store ---------------------------------
__global__ __launch_bounds__(256) void k5_out(float* __restrict__ out,
                                              int rows, int npair, int nt) {
    __shared__ int sW4[40], sb4[8];
    __shared__ float scmb3[32], sbsf3[32], sbsf4[8], scc[1];
    int t = threadIdx.x;
    if (t < 40) sW4[t] = g_W4p[t];
    if (t < 32) { scmb3[t] = g_cmb3[t]; sbsf3[t] = g_bsf3[t]; }
    if (t < 5) { sb4[t] = g_bint4[t]; sbsf4[t] = g_bsf4[t]; }
    if (t == 0) scc[0] = g_sf3;
    __syncthreads();
    float sf3 = scc[0];

    int gid = blockIdx.x * 256 + t;
#pragma unroll 1
    for (int p = gid; p < npair; p += nt) {
#pragma unroll
        for (int half = 0; half < 2; half++) {
            int row = p + half * npair;
            if (row >= rows) break;
            const uint4* pa = g_a3 + (size_t)row * 4;
            int q3[8];
#pragma unroll
            for (int c = 0; c < 4; c++) {
                uint4 v = pa[c];
                q3[c * 2 + 0] = quant4_i16(v.x, v.y, c * 8 + 0, scmb3, sbsf3, sf3);
                q3[c * 2 + 1] = quant4_i16(v.z, v.w, c * 8 + 4, scmb3, sbsf3, sf3);
            }
            float logit[5];
#pragma unroll
            for (int c = 0; c < 5; c++) {
                int acc = sb4[c];
#pragma unroll
                for (int k = 0; k < 8; k++) acc = dp4a_(q3[k], sW4[c * 8 + k], acc);
                logit[c] = __fmul_rn((float)acc, sbsf4[c]);
            }
            float m = logit[0];
#pragma unroll
            for (int c = 1; c < 5; c++) m = fmaxf(m, logit[c]);
            float e[5], s = 0.f;
#pragma unroll
            for (int c = 0; c < 5; c++) { e[c] = __expf(logit[c] - m); s += e[c]; }
            float rs = __frcp_rn(s);
            float* po = out + (size_t)row * 5;
#pragma unroll
            for (int c = 0; c < 5; c++) po[c] = e[c] * rs;
        }
    }
}

// ---- launcher --------------------------------------------------------------
extern "C" void kernel_launch(void* const* d_in, const int* in_sizes, int n_in,
                              void* d_out, int out_size) {
    const float* x  = (const float*)d_in[0];
    const float* W1 = (const float*)d_in[1];
    const float* b1 = (const float*)d_in[2];
    const float* W2 = (const float*)d_in[3];
    const float* b2 = (const float*)d_in[4];
    const float* W3 = (const float*)d_in[5];
    const float* b3 = (const float*)d_in[6];
    const float* W4 = (const float*)d_in[7];
    const float* b4 = (const float*)d_in[8];
    float* out = (float*)d_out;

    int rows = in_sizes[0] / 16;
    if (rows > ROWS_CAP) rows = ROWS_CAP;
    int npair = (rows + 1) / 2;

    int grid = (npair + 255) / 256;
    if (grid > 1184) grid = 1184;  // 148 SMs * 8 blocks
    int nt = grid * 256;

    k0_init<<<1, 256>>>(W1, W2, W3, W4);
    k1_absmax<<<1024, 256>>>(x, rows * 4);
    k1b_fin<<<1, 64>>>(b1);
    k2_l1<<<grid, 256>>>(x, rows, npair, nt);
    k2b_fin<<<1, 64>>>(b2);
    k3_l2<<<grid, 256>>>(rows, npair, nt);
    k3b_fin<<<1, 32>>>(b3);
    k4_l3<<<grid, 256>>>(rows, npair, nt);
    k4b_fin<<<1, 32>>>(b4);
    k5_out<<<grid, 256>>>(out, rows, npair, nt);
    (void)n_in; (void)out_size;
}

// round 6
// speedup vs baseline: 2.7588x; 1.1542x over previous
#include <cuda_runtime.h>
#include <cstdint>

// ---------------------------------------------------------------------------
// QThreeLayer: 6-bit quantized MLP 16 -> 64 -> 32 -> 32 -> 5, softmax.
// dp4a integer emulation, each layer computed exactly once.
// Inter-phase state: raw integer accumulators (acc1 i16, acc2 i32, acc3 i16).
// Activation-max tracked as a single scalar float per thread (exact:
// max_o,r float(acc)*bsf[o] == reference max|relu(h)|).
// ---------------------------------------------------------------------------

#define ROWS_CAP (1 << 20)

// ---- persistent device state (reset every replay by k0_init) --------------
__device__ unsigned int g_xmax;
__device__ unsigned int g_hmax1, g_hmax2, g_hmax3;  // float-as-uint, >= 0

__device__ int g_W1p[64 * 4];   // packed int8x4 weights, [o][k]
__device__ int g_W2p[32 * 16];
__device__ int g_W3p[32 * 8];
__device__ int g_W4p[8 * 8];    // padded to 8 rows for alignment
__device__ float g_wsc1[64], g_wsc2[32], g_wsc3[32], g_wsc4[5];

__device__ float g_sf0, g_inv0;
__device__ float g_sf1, g_sf2, g_sf3;
__device__ float g_bsf1[64], g_bsf2[32], g_bsf3[32], g_bsf4[5];
__device__ float g_cmb1[64], g_cmb2[32], g_cmb3[32];  // bsf/sf combined
__device__ int g_bint1[64], g_bint2[32], g_bint3[32], g_bint4[5];

// inter-phase accumulators
__device__ uint4 g_a1[ROWS_CAP * 8];  // L1 accs int16, 128 B/row
__device__ uint4 g_a2[ROWS_CAP * 8];  // L2 accs int32, 128 B/row
__device__ uint4 g_a3[ROWS_CAP * 4];  // L3 accs int16,  64 B/row

// ---- helpers ---------------------------------------------------------------
__device__ __forceinline__ int dp4a_(int a, int b, int c) {
    int d;
    asm("dp4a.s32.s32 %0, %1, %2, %3;" : "=r"(d) : "r"(a), "r"(b), "r"(c));
    return d;
}
__device__ __forceinline__ int iclamp(int v, int lo, int hi) {
    return v < lo ? lo : (v > hi ? hi : v);
}
__device__ __forceinline__ int pack4i(int a, int b, int c, int d) {
    return (a & 0xFF) | ((b & 0xFF) << 8) | ((c & 0xFF) << 16) | ((d & 0xFF) << 24);
}
__device__ __forceinline__ int lo16(unsigned u) { return (int)(u << 16) >> 16; }
__device__ __forceinline__ int hi16(unsigned u) { return (int)u >> 16; }

// round(t/s) with clip to [-32,31]; reciprocal fast path + exact IEEE
// fallback near .5 boundaries.
__device__ __forceinline__ int fquant(float t, float inv, float s) {
    float u = t * inv;
    float qa = rintf(u);
    if (0.5f - fabsf(u - qa) < 2e-5f) qa = rintf(__fdiv_rn(t, s));
    return iclamp((int)qa, -32, 31);
}

// quantize relu(acc*bsf)/sf where cmb = bsf/sf precomputed; result in [0,31]
__device__ __forceinline__ int fquant_pos(float accf, float cmb, float bsf, float sf) {
    float u = fmaxf(accf * cmb, 0.f);
    float qa = rintf(u);
    if (0.5f - fabsf(u - qa) < 2e-5f) {
        float h = fmaxf(__fmul_rn(accf, bsf), 0.f);
        qa = rintf(__fdiv_rn(h, sf));
    }
    int q = (int)qa;
    return q > 31 ? 31 : q;
}

// quantize 4 int16-acc channels (from two packed uints) into one int8x4 word
__device__ __forceinline__ int quant4_i16(unsigned u0, unsigned u1, int ob,
                                          const float* cmb, const float* bsf, float sf) {
    int a = fquant_pos((float)lo16(u0), cmb[ob + 0], bsf[ob + 0], sf);
    int b = fquant_pos((float)hi16(u0), cmb[ob + 1], bsf[ob + 1], sf);
    int c = fquant_pos((float)lo16(u1), cmb[ob + 2], bsf[ob + 2], sf);
    int d = fquant_pos((float)hi16(u1), cmb[ob + 3], bsf[ob + 3], sf);
    return pack4i(a, b, c, d);
}

__device__ __forceinline__ void warp_fmax_atomic(float m, unsigned* dst) {
#pragma unroll
    for (int s = 16; s; s >>= 1) m = fmaxf(m, __shfl_xor_sync(0xffffffffu, m, s));
    if ((threadIdx.x & 31) == 0) atomicMax(dst, __float_as_uint(m));
}

// ---- K0: reset reductions + quantize weights ------------------------------
__global__ void k0_init(const float* __restrict__ W1, const float* __restrict__ W2,
                        const float* __restrict__ W3, const float* __restrict__ W4) {
    int t = threadIdx.x;
    if (t == 0) { g_xmax = 0u; g_hmax1 = 0u; g_hmax2 = 0u; g_hmax3 = 0u; }
    if (t < 24) g_W4p[40 + t] = 0;  // pad

    if (t < 64) {  // layer 1: [64,16]
        const float* w = W1 + t * 16;
        float m = 0.f;
#pragma unroll
        for (int i = 0; i < 16; i++) m = fmaxf(m, fabsf(w[i]));
        float sc = __fdiv_rn(fmaxf(m, 1e-8f), 31.0f);
        g_wsc1[t] = sc;
#pragma unroll
        for (int k = 0; k < 4; k++) {
            int a = iclamp((int)rintf(__fdiv_rn(w[4 * k + 0], sc)), -32, 31);
            int b = iclamp((int)rintf(__fdiv_rn(w[4 * k + 1], sc)), -32, 31);
            int c = iclamp((int)rintf(__fdiv_rn(w[4 * k + 2], sc)), -32, 31);
            int d = iclamp((int)rintf(__fdiv_rn(w[4 * k + 3], sc)), -32, 31);
            g_W1p[t * 4 + k] = pack4i(a, b, c, d);
        }
    } else if (t < 96) {  // layer 2: [32,64]
        int o = t - 64;
        const float* w = W2 + o * 64;
        float m = 0.f;
#pragma unroll
        for (int i = 0; i < 64; i++) m = fmaxf(m, fabsf(w[i]));
        float sc = __fdiv_rn(fmaxf(m, 1e-8f), 31.0f);
        g_wsc2[o] = sc;
#pragma unroll
        for (int k = 0; k < 16; k++) {
            int a = iclamp((int)rintf(__fdiv_rn(w[4 * k + 0], sc)), -32, 31);
            int b = iclamp((int)rintf(__fdiv_rn(w[4 * k + 1], sc)), -32, 31);
            int c = iclamp((int)rintf(__fdiv_rn(w[4 * k + 2], sc)), -32, 31);
            int d = iclamp((int)rintf(__fdiv_rn(w[4 * k + 3], sc)), -32, 31);
            g_W2p[o * 16 + k] = pack4i(a, b, c, d);
        }
    } else if (t < 128) {  // layer 3: [32,32]
        int o = t - 96;
        const float* w = W3 + o * 32;
        float m = 0.f;
#pragma unroll
        for (int i = 0; i < 32; i++) m = fmaxf(m, fabsf(w[i]));
        float sc = __fdiv_rn(fmaxf(m, 1e-8f), 31.0f);
        g_wsc3[o] = sc;
#pragma unroll
        for (int k = 0; k < 8; k++) {
            int a = iclamp((int)rintf(__fdiv_rn(w[4 * k + 0], sc)), -32, 31);
            int b = iclamp((int)rintf(__fdiv_rn(w[4 * k + 1], sc)), -32, 31);
            int c = iclamp((int)rintf(__fdiv_rn(w[4 * k + 2], sc)), -32, 31);
            int d = iclamp((int)rintf(__fdiv_rn(w[4 * k + 3], sc)), -32, 31);
            g_W3p[o * 8 + k] = pack4i(a, b, c, d);
        }
    } else if (t < 133) {  // layer 4: [5,32]
        int o = t - 128;
        const float* w = W4 + o * 32;
        float m = 0.f;
#pragma unroll
        for (int i = 0; i < 32; i++) m = fmaxf(m, fabsf(w[i]));
        float sc = __fdiv_rn(fmaxf(m, 1e-8f), 31.0f);
        g_wsc4[o] = sc;
#pragma unroll
        for (int k = 0; k < 8; k++) {
            int a = iclamp((int)rintf(__fdiv_rn(w[4 * k + 0], sc)), -32, 31);
            int b = iclamp((int)rintf(__fdiv_rn(w[4 * k + 1], sc)), -32, 31);
            int c = iclamp((int)rintf(__fdiv_rn(w[4 * k + 2], sc)), -32, 31);
            int d = iclamp((int)rintf(__fdiv_rn(w[4 * k + 3], sc)), -32, 31);
            g_W4p[o * 8 + k] = pack4i(a, b, c, d);
        }
    }
}

// ---- K1: global max|x| -----------------------------------------------------
__global__ void k1_absmax(const float* __restrict__ x, int n4) {
    const float4* x4 = (const float4*)x;
    int i = blockIdx.x * blockDim.x + threadIdx.x;
    int stride = gridDim.x * blockDim.x;
    float m = 0.f;
    for (; i < n4; i += stride) {
        float4 v = x4[i];
        m = fmaxf(m, fmaxf(fmaxf(fabsf(v.x), fabsf(v.y)), fmaxf(fabsf(v.z), fabsf(v.w))));
    }
    warp_fmax_atomic(m, &g_xmax);
}

// ---- K1b: sf0, layer-1 bias quant -----------------------------------------
__global__ void k1b_fin(const float* __restrict__ b1) {
    __shared__ float ssf;
    int t = threadIdx.x;
    if (t == 0) {
        float sf = __fdiv_rn(fmaxf(__uint_as_float(g_xmax), 1e-8f), 31.0f);
        g_sf0 = sf;
        g_inv0 = __fdiv_rn(1.0f, sf);
        ssf = sf;
    }
    __syncthreads();
    if (t < 64) {
        float bsf = __fmul_rn(g_wsc1[t], ssf);
        g_bsf1[t] = bsf;
        g_bint1[t] = iclamp((int)rintf(__fdiv_rn(b1[t], bsf)), -32, 31);
    }
}

// ---- K2: x -> q0 (regs) -> L1, store acc1 i16, scalar h-max ---------------
__global__ __launch_bounds__(256) void k2_l1(const float* __restrict__ x,
                                             int rows, int nt) {
    __shared__ int4 sW[64];
    __shared__ int sb[64];
    __shared__ float sbsf[64], sc0[2];
    int t = threadIdx.x;
    if (t < 64) {
        sW[t] = ((const int4*)g_W1p)[t];
        sb[t] = g_bint1[t];
        sbsf[t] = g_bsf1[t];
    }
    if (t == 0) { sc0[0] = g_inv0; sc0[1] = g_sf0; }
    __syncthreads();
    float inv0 = sc0[0], sf0 = sc0[1];
    float m = 0.f;

    const float4* x4 = (const float4*)x;
#pragma unroll 1
    for (int row = blockIdx.x * 256 + t; row < rows; row += nt) {
        int qa[4];
#pragma unroll
        for (int j = 0; j < 4; j++) {
            float4 v = x4[(size_t)row * 4 + j];
            qa[j] = pack4i(fquant(v.x, inv0, sf0), fquant(v.y, inv0, sf0),
                           fquant(v.z, inv0, sf0), fquant(v.w, inv0, sf0));
        }
        uint4* prow = g_a1 + (size_t)row * 8;
#pragma unroll
        for (int g = 0; g < 8; g++) {
            unsigned w[4];
#pragma unroll
            for (int j = 0; j < 4; j++) {
                int o0 = g * 8 + 2 * j, o1 = o0 + 1;
                int4 w0 = sW[o0], w1 = sW[o1];
                int a0 = sb[o0], a1 = sb[o1];
                a0 = dp4a_(qa[0], w0.x, a0); a0 = dp4a_(qa[1], w0.y, a0);
                a0 = dp4a_(qa[2], w0.z, a0); a0 = dp4a_(qa[3], w0.w, a0);
                a1 = dp4a_(qa[0], w1.x, a1); a1 = dp4a_(qa[1], w1.y, a1);
                a1 = dp4a_(qa[2], w1.z, a1); a1 = dp4a_(qa[3], w1.w, a1);
                m = fmaxf(m, __fmul_rn((float)a0, sbsf[o0]));
                m = fmaxf(m, __fmul_rn((float)a1, sbsf[o1]));
                w[j] = ((unsigned)a0 & 0xFFFFu) | ((unsigned)a1 << 16);
            }
            prow[g] = make_uint4(w[0], w[1], w[2], w[3]);
        }
    }
    warp_fmax_atomic(m, &g_hmax1);
}

// ---- K2b: sf1, cmb1, layer-2 bias quant -----------------------------------
__global__ void k2b_fin(const float* __restrict__ b2) {
    __shared__ float s_sf, s_inv;
    int t = threadIdx.x;  // 64 threads
    if (t == 0) {
        float sf = __fdiv_rn(fmaxf(__uint_as_float(g_hmax1), 1e-8f), 31.0f);
        g_sf1 = sf;
        s_sf = sf;
        s_inv = __fdiv_rn(1.0f, sf);
    }
    __syncthreads();
    g_cmb1[t] = __fmul_rn(g_bsf1[t], s_inv);
    if (t < 32) {
        float bsf = __fmul_rn(g_wsc2[t], s_sf);
        g_bsf2[t] = bsf;
        g_bint2[t] = iclamp((int)rintf(__fdiv_rn(b2[t], bsf)), -32, 31);
    }
}

// ---- K3: acc1 -> q1 -> L2, store acc2 i32, scalar h-max -------------------
__global__ __launch_bounds__(256) void k3_l2(int rows, int nt) {
    __shared__ int4 sW2[128];
    __shared__ int sb2[32];
    __shared__ float scmb1[64], sbsf1[64], sbsf2[32], scc[1];
    int t = threadIdx.x;
    if (t < 128) sW2[t] = ((const int4*)g_W2p)[t];
    if (t < 64) { scmb1[t] = g_cmb1[t]; sbsf1[t] = g_bsf1[t]; }
    if (t < 32) { sb2[t] = g_bint2[t]; sbsf2[t] = g_bsf2[t]; }
    if (t == 0) scc[0] = g_sf1;
    __syncthreads();
    float sf1 = scc[0];
    float m = 0.f;

#pragma unroll 1
    for (int row = blockIdx.x * 256 + t; row < rows; row += nt) {
        const uint4* pa = g_a1 + (size_t)row * 8;
        int q1[16];
#pragma unroll
        for (int c = 0; c < 8; c++) {
            uint4 v = pa[c];
            q1[c * 2 + 0] = quant4_i16(v.x, v.y, c * 8 + 0, scmb1, sbsf1, sf1);
            q1[c * 2 + 1] = quant4_i16(v.z, v.w, c * 8 + 4, scmb1, sbsf1, sf1);
        }
        uint4* orow = g_a2 + (size_t)row * 8;
#pragma unroll
        for (int g = 0; g < 8; g++) {
            int w[4];
#pragma unroll
            for (int j = 0; j < 4; j++) {
                int o = g * 4 + j;
                int acc = sb2[o];
#pragma unroll
                for (int kk = 0; kk < 4; kk++) {
                    int4 wv = sW2[o * 4 + kk];
                    acc = dp4a_(q1[kk * 4 + 0], wv.x, acc);
                    acc = dp4a_(q1[kk * 4 + 1], wv.y, acc);
                    acc = dp4a_(q1[kk * 4 + 2], wv.z, acc);
                    acc = dp4a_(q1[kk * 4 + 3], wv.w, acc);
                }
                m = fmaxf(m, __fmul_rn((float)acc, sbsf2[o]));
                w[j] = acc;
            }
            orow[g] = make_uint4((unsigned)w[0], (unsigned)w[1],
                                 (unsigned)w[2], (unsigned)w[3]);
        }
    }
    warp_fmax_atomic(m, &g_hmax2);
}

// ---- K3b: sf2, cmb2, layer-3 bias quant -----------------------------------
__global__ void k3b_fin(const float* __restrict__ b3) {
    __shared__ float s_sf, s_inv;
    int t = threadIdx.x;  // 32 threads
    if (t == 0) {
        float sf = __fdiv_rn(fmaxf(__uint_as_float(g_hmax2), 1e-8f), 31.0f);
        g_sf2 = sf;
        s_sf = sf;
        s_inv = __fdiv_rn(1.0f, sf);
    }
    __syncthreads();
    g_cmb2[t] = __fmul_rn(g_bsf2[t], s_inv);
    {
        float bsf = __fmul_rn(g_wsc3[t], s_sf);
        g_bsf3[t] = bsf;
        g_bint3[t] = iclamp((int)rintf(__fdiv_rn(b3[t], bsf)), -32, 31);
    }
}

// ---- K4: acc2 -> q2 -> L3, store acc3 i16, scalar h-max -------------------
__global__ __launch_bounds__(256) void k4_l3(int rows, int nt) {
    __shared__ int4 sW3[64];
    __shared__ int sb3[32];
    __shared__ float scmb2[32], sbsf2[32], sbsf3[32], scc[1];
    int t = threadIdx.x;
    if (t < 64) sW3[t] = ((const int4*)g_W3p)[t];
    if (t < 32) {
        scmb2[t] = g_cmb2[t];
        sbsf2[t] = g_bsf2[t];
        sb3[t] = g_bint3[t];
        sbsf3[t] = g_bsf3[t];
    }
    if (t == 0) scc[0] = g_sf2;
    __syncthreads();
    float sf2 = scc[0];
    float m = 0.f;

#pragma unroll 1
    for (int row = blockIdx.x * 256 + t; row < rows; row += nt) {
        const uint4* pa = g_a2 + (size_t)row * 8;
        int q2[8];
#pragma unroll
        for (int c = 0; c < 8; c++) {
            uint4 v = pa[c];
            int ob = c * 4;
            q2[c] = pack4i(
                fquant_pos((float)(int)v.x, scmb2[ob + 0], sbsf2[ob + 0], sf2),
                fquant_pos((float)(int)v.y, scmb2[ob + 1], sbsf2[ob + 1], sf2),
                fquant_pos((float)(int)v.z, scmb2[ob + 2], sbsf2[ob + 2], sf2),
                fquant_pos((float)(int)v.w, scmb2[ob + 3], sbsf2[ob + 3], sf2));
        }
        uint4* orow = g_a3 + (size_t)row * 4;
#pragma unroll
        for (int g = 0; g < 4; g++) {
            unsigned w[4];
#pragma unroll
            for (int j = 0; j < 4; j++) {
                int o0 = g * 8 + 2 * j, o1 = o0 + 1;
                int4 wa = sW3[o0 * 2], wb = sW3[o0 * 2 + 1];
                int4 wc = sW3[o1 * 2], wd = sW3[o1 * 2 + 1];
                int a0 = sb3[o0], a1 = sb3[o1];
                a0 = dp4a_(q2[0], wa.x, a0); a0 = dp4a_(q2[1], wa.y, a0);
                a0 = dp4a_(q2[2], wa.z, a0); a0 = dp4a_(q2[3], wa.w, a0);
                a0 = dp4a_(q2[4], wb.x, a0); a0 = dp4a_(q2[5], wb.y, a0);
                a0 = dp4a_(q2[6], wb.z, a0); a0 = dp4a_(q2[7], wb.w, a0);
                a1 = dp4a_(q2[0], wc.x, a1); a1 = dp4a_(q2[1], wc.y, a1);
                a1 = dp4a_(q2[2], wc.z, a1); a1 = dp4a_(q2[3], wc.w, a1);
                a1 = dp4a_(q2[4], wd.x, a1); a1 = dp4a_(q2[5], wd.y, a1);
                a1 = dp4a_(q2[6], wd.z, a1); a1 = dp4a_(q2[7], wd.w, a1);
                m = fmaxf(m, __fmul_rn((float)a0, sbsf3[o0]));
                m = fmaxf(m, __fmul_rn((float)a1, sbsf3[o1]));
                w[j] = ((unsigned)a0 & 0xFFFFu) | ((unsigned)a1 << 16);
            }
            orow[g] = make_uint4(w[0], w[1], w[2], w[3]);
        }
    }
    warp_fmax_atomic(m, &g_hmax3);
}

// ---- K4b: sf3, cmb3, layer-4 bias quant -----------------------------------
__global__ void k4b_fin(const float* __restrict__ b4) {
    __shared__ float s_sf, s_inv;
    int t = threadIdx.x;  // 32 threads
    if (t == 0) {
        float sf = __fdiv_rn(fmaxf(__uint_as_float(g_hmax3), 1e-8f), 31.0f);
        g_sf3 = sf;
        s_sf = sf;
        s_inv = __fdiv_rn(1.0f, sf);
    }
    __syncthreads();
    g_cmb3[t] = __fmul_rn(g_bsf3[t], s_inv);
    if (t < 5) {
        float bsf = __fmul_rn(g_wsc4[t], s_sf);
        g_bsf4[t] = bsf;
        g_bint4[t] = iclamp((int)rintf(__fdiv_rn(b4[t], bsf)), -32, 31);
    }
}

// ---- K5: acc3 -> q3 -> L4, softmax, store ---------------------------------
__global__ __launch_bounds__(256) void k5_out(float* __restrict__ out,
                                              int rows, int nt) {
    __shared__ int4 sW4[10];
    __shared__ int sb4[8];
    __shared__ float scmb3[32], sbsf3[32], sbsf4[8], scc[1];
    int t = threadIdx.x;
    if (t < 10) sW4[t] = ((const int4*)g_W4p)[t];
    if (t < 32) { scmb3[t] = g_cmb3[t]; sbsf3[t] = g_bsf3[t]; }
    if (t < 5) { sb4[t] = g_bint4[t]; sbsf4[t] = g_bsf4[t]; }
    if (t == 0) scc[0] = g_sf3;
    __syncthreads();
    float sf3 = scc[0];

#pragma unroll 1
    for (int row = blockIdx.x * 256 + t; row < rows; row += nt) {
        const uint4* pa = g_a3 + (size_t)row * 4;
        int q3[8];
#pragma unroll
        for (int c = 0; c < 4; c++) {
            uint4 v = pa[c];
            q3[c * 2 + 0] = quant4_i16(v.x, v.y, c * 8 + 0, scmb3, sbsf3, sf3);
            q3[c * 2 + 1] = quant4_i16(v.z, v.w, c * 8 + 4, scmb3, sbsf3, sf3);
        }
        float logit[5];
#pragma unroll
        for (int c = 0; c < 5; c++) {
            int4 wa = sW4[c * 2], wb = sW4[c * 2 + 1];
            int acc = sb4[c];
            acc = dp4a_(q3[0], wa.x, acc); acc = dp4a_(q3[1], wa.y, acc);
            acc = dp4a_(q3[2], wa.z, acc); acc = dp4a_(q3[3], wa.w, acc);
            acc = dp4a_(q3[4], wb.x, acc); acc = dp4a_(q3[5], wb.y, acc);
            acc = dp4a_(q3[6], wb.z, acc); acc = dp4a_(q3[7], wb.w, acc);
            logit[c] = __fmul_rn((float)acc, sbsf4[c]);
        }
        float mm = logit[0];
#pragma unroll
        for (int c = 1; c < 5; c++) mm = fmaxf(mm, logit[c]);
        float e[5], s = 0.f;
#pragma unroll
        for (int c = 0; c < 5; c++) { e[c] = __expf(logit[c] - mm); s += e[c]; }
        float rs = __frcp_rn(s);
        float* po = out + (size_t)row * 5;
#pragma unroll
        for (int c = 0; c < 5; c++) po[c] = e[c] * rs;
    }
}

// ---- launcher --------------------------------------------------------------
extern "C" void kernel_launch(void* const* d_in, const int* in_sizes, int n_in,
                              void* d_out, int out_size) {
    const float* x  = (const float*)d_in[0];
    const float* W1 = (const float*)d_in[1];
    const float* b1 = (const float*)d_in[2];
    const float* W2 = (const float*)d_in[3];
    const float* b2 = (const float*)d_in[4];
    const float* W3 = (const float*)d_in[5];
    const float* b3 = (const float*)d_in[6];
    const float* W4 = (const float*)d_in[7];
    const float* b4 = (const float*)d_in[8];
    float* out = (float*)d_out;

    int rows = in_sizes[0] / 16;
    if (rows > ROWS_CAP) rows = ROWS_CAP;

    int grid = (rows + 255) / 256;
    if (grid > 2368) grid = 2368;  // 148 SMs * 16 blocks
    int nt = grid * 256;

    k0_init<<<1, 256>>>(W1, W2, W3, W4);
    k1_absmax<<<1024, 256>>>(x, rows * 4);
    k1b_fin<<<1, 64>>>(b1);
    k2_l1<<<grid, 256>>>(x, rows, nt);
    k2b_fin<<<1, 64>>>(b2);
    k3_l2<<<grid, 256>>>(rows, nt);
    k3b_fin<<<1, 32>>>(b3);
    k4_l3<<<grid, 256>>>(rows, nt);
    k4b_fin<<<1, 32>>>(b4);
    k5_out<<<grid, 256>>>(out, rows, nt);
    (void)n_in; (void)out_size;
}

// round 7
// speedup vs baseline: 3.5745x; 1.2957x over previous
#include <cuda_runtime.h>
#include <cstdint>

// ---------------------------------------------------------------------------
// QThreeLayer: 6-bit quantized MLP 16 -> 64 -> 32 -> 32 -> 5, softmax.
// dp4a integer emulation, each layer computed exactly once.
// Inter-phase state: raw integer accumulators (acc1 i16, acc2 i32, acc3 i16).
// Round 7: __launch_bounds__(256,2) caps regs at 128 -> 2 CTAs/SM (occ 25%).
// ---------------------------------------------------------------------------

#define ROWS_CAP (1 << 20)

// ---- persistent device state (reset every replay by k0_init) --------------
__device__ unsigned int g_xmax;
__device__ unsigned int g_hmax1, g_hmax2, g_hmax3;  // float-as-uint, >= 0

__device__ int g_W1p[64 * 4];   // packed int8x4 weights, [o][k]
__device__ int g_W2p[32 * 16];
__device__ int g_W3p[32 * 8];
__device__ int g_W4p[8 * 8];    // padded to 8 rows for alignment
__device__ float g_wsc1[64], g_wsc2[32], g_wsc3[32], g_wsc4[5];

__device__ float g_sf0, g_inv0;
__device__ float g_sf1, g_sf2, g_sf3;
__device__ float g_bsf1[64], g_bsf2[32], g_bsf3[32], g_bsf4[5];
__device__ float g_cmb1[64], g_cmb2[32], g_cmb3[32];  // bsf/sf combined
__device__ int g_bint1[64], g_bint2[32], g_bint3[32], g_bint4[5];

// inter-phase accumulators
__device__ uint4 g_a1[ROWS_CAP * 8];  // L1 accs int16, 128 B/row
__device__ uint4 g_a2[ROWS_CAP * 8];  // L2 accs int32, 128 B/row
__device__ uint4 g_a3[ROWS_CAP * 4];  // L3 accs int16,  64 B/row

// ---- helpers ---------------------------------------------------------------
__device__ __forceinline__ int dp4a_(int a, int b, int c) {
    int d;
    asm("dp4a.s32.s32 %0, %1, %2, %3;" : "=r"(d) : "r"(a), "r"(b), "r"(c));
    return d;
}
__device__ __forceinline__ int iclamp(int v, int lo, int hi) {
    return v < lo ? lo : (v > hi ? hi : v);
}
__device__ __forceinline__ int pack4i(int a, int b, int c, int d) {
    return (a & 0xFF) | ((b & 0xFF) << 8) | ((c & 0xFF) << 16) | ((d & 0xFF) << 24);
}
__device__ __forceinline__ int lo16(unsigned u) { return (int)(u << 16) >> 16; }
__device__ __forceinline__ int hi16(unsigned u) { return (int)u >> 16; }

// round(t/s) with clip to [-32,31]; reciprocal fast path + exact IEEE
// fallback near .5 boundaries.
__device__ __forceinline__ int fquant(float t, float inv, float s) {
    float u = t * inv;
    float qa = rintf(u);
    if (0.5f - fabsf(u - qa) < 2e-5f) qa = rintf(__fdiv_rn(t, s));
    return iclamp((int)qa, -32, 31);
}

// quantize relu(acc*bsf)/sf where cmb = bsf/sf precomputed; result in [0,31]
__device__ __forceinline__ int fquant_pos(float accf, float cmb, float bsf, float sf) {
    float u = fmaxf(accf * cmb, 0.f);
    float qa = rintf(u);
    if (0.5f - fabsf(u - qa) < 2e-5f) {
        float h = fmaxf(__fmul_rn(accf, bsf), 0.f);
        qa = rintf(__fdiv_rn(h, sf));
    }
    int q = (int)qa;
    return q > 31 ? 31 : q;
}

// quantize 4 int16-acc channels (from two packed uints) into one int8x4 word
__device__ __forceinline__ int quant4_i16(unsigned u0, unsigned u1, int ob,
                                          const float* cmb, const float* bsf, float sf) {
    int a = fquant_pos((float)lo16(u0), cmb[ob + 0], bsf[ob + 0], sf);
    int b = fquant_pos((float)hi16(u0), cmb[ob + 1], bsf[ob + 1], sf);
    int c = fquant_pos((float)lo16(u1), cmb[ob + 2], bsf[ob + 2], sf);
    int d = fquant_pos((float)hi16(u1), cmb[ob + 3], bsf[ob + 3], sf);
    return pack4i(a, b, c, d);
}

__device__ __forceinline__ void warp_fmax_atomic(float m, unsigned* dst) {
#pragma unroll
    for (int s = 16; s; s >>= 1) m = fmaxf(m, __shfl_xor_sync(0xffffffffu, m, s));
    if ((threadIdx.x & 31) == 0) atomicMax(dst, __float_as_uint(m));
}

// ---- K0: reset reductions + quantize weights ------------------------------
__global__ void k0_init(const float* __restrict__ W1, const float* __restrict__ W2,
                        const float* __restrict__ W3, const float* __restrict__ W4) {
    int t = threadIdx.x;
    if (t == 0) { g_xmax = 0u; g_hmax1 = 0u; g_hmax2 = 0u; g_hmax3 = 0u; }
    if (t < 24) g_W4p[40 + t] = 0;  // pad

    if (t < 64) {  // layer 1: [64,16]
        const float* w = W1 + t * 16;
        float m = 0.f;
#pragma unroll
        for (int i = 0; i < 16; i++) m = fmaxf(m, fabsf(w[i]));
        float sc = __fdiv_rn(fmaxf(m, 1e-8f), 31.0f);
        g_wsc1[t] = sc;
#pragma unroll
        for (int k = 0; k < 4; k++) {
            int a = iclamp((int)rintf(__fdiv_rn(w[4 * k + 0], sc)), -32, 31);
            int b = iclamp((int)rintf(__fdiv_rn(w[4 * k + 1], sc)), -32, 31);
            int c = iclamp((int)rintf(__fdiv_rn(w[4 * k + 2], sc)), -32, 31);
            int d = iclamp((int)rintf(__fdiv_rn(w[4 * k + 3], sc)), -32, 31);
            g_W1p[t * 4 + k] = pack4i(a, b, c, d);
        }
    } else if (t < 96) {  // layer 2: [32,64]
        int o = t - 64;
        const float* w = W2 + o * 64;
        float m = 0.f;
#pragma unroll
        for (int i = 0; i < 64; i++) m = fmaxf(m, fabsf(w[i]));
        float sc = __fdiv_rn(fmaxf(m, 1e-8f), 31.0f);
        g_wsc2[o] = sc;
#pragma unroll
        for (int k = 0; k < 16; k++) {
            int a = iclamp((int)rintf(__fdiv_rn(w[4 * k + 0], sc)), -32, 31);
            int b = iclamp((int)rintf(__fdiv_rn(w[4 * k + 1], sc)), -32, 31);
            int c = iclamp((int)rintf(__fdiv_rn(w[4 * k + 2], sc)), -32, 31);
            int d = iclamp((int)rintf(__fdiv_rn(w[4 * k + 3], sc)), -32, 31);
            g_W2p[o * 16 + k] = pack4i(a, b, c, d);
        }
    } else if (t < 128) {  // layer 3: [32,32]
        int o = t - 96;
        const float* w = W3 + o * 32;
        float m = 0.f;
#pragma unroll
        for (int i = 0; i < 32; i++) m = fmaxf(m, fabsf(w[i]));
        float sc = __fdiv_rn(fmaxf(m, 1e-8f), 31.0f);
        g_wsc3[o] = sc;
#pragma unroll
        for (int k = 0; k < 8; k++) {
            int a = iclamp((int)rintf(__fdiv_rn(w[4 * k + 0], sc)), -32, 31);
            int b = iclamp((int)rintf(__fdiv_rn(w[4 * k + 1], sc)), -32, 31);
            int c = iclamp((int)rintf(__fdiv_rn(w[4 * k + 2], sc)), -32, 31);
            int d = iclamp((int)rintf(__fdiv_rn(w[4 * k + 3], sc)), -32, 31);
            g_W3p[o * 8 + k] = pack4i(a, b, c, d);
        }
    } else if (t < 133) {  // layer 4: [5,32]
        int o = t - 128;
        const float* w = W4 + o * 32;
        float m = 0.f;
#pragma unroll
        for (int i = 0; i < 32; i++) m = fmaxf(m, fabsf(w[i]));
        float sc = __fdiv_rn(fmaxf(m, 1e-8f), 31.0f);
        g_wsc4[o] = sc;
#pragma unroll
        for (int k = 0; k < 8; k++) {
            int a = iclamp((int)rintf(__fdiv_rn(w[4 * k + 0], sc)), -32, 31);
            int b = iclamp((int)rintf(__fdiv_rn(w[4 * k + 1], sc)), -32, 31);
            int c = iclamp((int)rintf(__fdiv_rn(w[4 * k + 2], sc)), -32, 31);
            int d = iclamp((int)rintf(__fdiv_rn(w[4 * k + 3], sc)), -32, 31);
            g_W4p[o * 8 + k] = pack4i(a, b, c, d);
        }
    }
}

// ---- K1: global max|x| -----------------------------------------------------
__global__ void k1_absmax(const float* __restrict__ x, int n4) {
    const float4* x4 = (const float4*)x;
    int i = blockIdx.x * blockDim.x + threadIdx.x;
    int stride = gridDim.x * blockDim.x;
    float m = 0.f;
    for (; i < n4; i += stride) {
        float4 v = x4[i];
        m = fmaxf(m, fmaxf(fmaxf(fabsf(v.x), fabsf(v.y)), fmaxf(fabsf(v.z), fabsf(v.w))));
    }
    warp_fmax_atomic(m, &g_xmax);
}

// ---- K1b: sf0, layer-1 bias quant -----------------------------------------
__global__ void k1b_fin(const float* __restrict__ b1) {
    __shared__ float ssf;
    int t = threadIdx.x;
    if (t == 0) {
        float sf = __fdiv_rn(fmaxf(__uint_as_float(g_xmax), 1e-8f), 31.0f);
        g_sf0 = sf;
        g_inv0 = __fdiv_rn(1.0f, sf);
        ssf = sf;
    }
    __syncthreads();
    if (t < 64) {
        float bsf = __fmul_rn(g_wsc1[t], ssf);
        g_bsf1[t] = bsf;
        g_bint1[t] = iclamp((int)rintf(__fdiv_rn(b1[t], bsf)), -32, 31);
    }
}

// ---- K2: x -> q0 (regs) -> L1, store acc1 i16, scalar h-max ---------------
__global__ __launch_bounds__(256, 2) void k2_l1(const float* __restrict__ x,
                                                int rows, int nt) {
    __shared__ int4 sW[64];
    __shared__ int sb[64];
    __shared__ float sbsf[64], sc0[2];
    int t = threadIdx.x;
    if (t < 64) {
        sW[t] = ((const int4*)g_W1p)[t];
        sb[t] = g_bint1[t];
        sbsf[t] = g_bsf1[t];
    }
    if (t == 0) { sc0[0] = g_inv0; sc0[1] = g_sf0; }
    __syncthreads();
    float inv0 = sc0[0], sf0 = sc0[1];
    float m = 0.f;

    const float4* x4 = (const float4*)x;
#pragma unroll 1
    for (int row = blockIdx.x * 256 + t; row < rows; row += nt) {
        int qa[4];
#pragma unroll
        for (int j = 0; j < 4; j++) {
            float4 v = x4[(size_t)row * 4 + j];
            qa[j] = pack4i(fquant(v.x, inv0, sf0), fquant(v.y, inv0, sf0),
                           fquant(v.z, inv0, sf0), fquant(v.w, inv0, sf0));
        }
        uint4* prow = g_a1 + (size_t)row * 8;
#pragma unroll
        for (int g = 0; g < 8; g++) {
            unsigned w[4];
#pragma unroll
            for (int j = 0; j < 4; j++) {
                int o0 = g * 8 + 2 * j, o1 = o0 + 1;
                int4 w0 = sW[o0], w1 = sW[o1];
                int a0 = sb[o0], a1 = sb[o1];
                a0 = dp4a_(qa[0], w0.x, a0); a0 = dp4a_(qa[1], w0.y, a0);
                a0 = dp4a_(qa[2], w0.z, a0); a0 = dp4a_(qa[3], w0.w, a0);
                a1 = dp4a_(qa[0], w1.x, a1); a1 = dp4a_(qa[1], w1.y, a1);
                a1 = dp4a_(qa[2], w1.z, a1); a1 = dp4a_(qa[3], w1.w, a1);
                m = fmaxf(m, __fmul_rn((float)a0, sbsf[o0]));
                m = fmaxf(m, __fmul_rn((float)a1, sbsf[o1]));
                w[j] = ((unsigned)a0 & 0xFFFFu) | ((unsigned)a1 << 16);
            }
            prow[g] = make_uint4(w[0], w[1], w[2], w[3]);
        }
    }
    warp_fmax_atomic(m, &g_hmax1);
}

// ---- K2b: sf1, cmb1, layer-2 bias quant -----------------------------------
__global__ void k2b_fin(const float* __restrict__ b2) {
    __shared__ float s_sf, s_inv;
    int t = threadIdx.x;  // 64 threads
    if (t == 0) {
        float sf = __fdiv_rn(fmaxf(__uint_as_float(g_hmax1), 1e-8f), 31.0f);
        g_sf1 = sf;
        s_sf = sf;
        s_inv = __fdiv_rn(1.0f, sf);
    }
    __syncthreads();
    g_cmb1[t] = __fmul_rn(g_bsf1[t], s_inv);
    if (t < 32) {
        float bsf = __fmul_rn(g_wsc2[t], s_sf);
        g_bsf2[t] = bsf;
        g_bint2[t] = iclamp((int)rintf(__fdiv_rn(b2[t], bsf)), -32, 31);
    }
}

// ---- K3: acc1 -> q1 -> L2, store acc2 i32, scalar h-max -------------------
__global__ __launch_bounds__(256, 2) void k3_l2(int rows, int nt) {
    __shared__ int4 sW2[128];
    __shared__ int sb2[32];
    __shared__ float scmb1[64], sbsf1[64], sbsf2[32], scc[1];
    int t = threadIdx.x;
    if (t < 128) sW2[t] = ((const int4*)g_W2p)[t];
    if (t < 64) { scmb1[t] = g_cmb1[t]; sbsf1[t] = g_bsf1[t]; }
    if (t < 32) { sb2[t] = g_bint2[t]; sbsf2[t] = g_bsf2[t]; }
    if (t == 0) scc[0] = g_sf1;
    __syncthreads();
    float sf1 = scc[0];
    float m = 0.f;

#pragma unroll 1
    for (int row = blockIdx.x * 256 + t; row < rows; row += nt) {
        const uint4* pa = g_a1 + (size_t)row * 8;
        int q1[16];
#pragma unroll
        for (int c = 0; c < 8; c++) {
            uint4 v = pa[c];
            q1[c * 2 + 0] = quant4_i16(v.x, v.y, c * 8 + 0, scmb1, sbsf1, sf1);
            q1[c * 2 + 1] = quant4_i16(v.z, v.w, c * 8 + 4, scmb1, sbsf1, sf1);
        }
        uint4* orow = g_a2 + (size_t)row * 8;
#pragma unroll
        for (int g = 0; g < 8; g++) {
            int w[4];
#pragma unroll
            for (int j = 0; j < 4; j++) {
                int o = g * 4 + j;
                int acc = sb2[o];
#pragma unroll
                for (int kk = 0; kk < 4; kk++) {
                    int4 wv = sW2[o * 4 + kk];
                    acc = dp4a_(q1[kk * 4 + 0], wv.x, acc);
                    acc = dp4a_(q1[kk * 4 + 1], wv.y, acc);
                    acc = dp4a_(q1[kk * 4 + 2], wv.z, acc);
                    acc = dp4a_(q1[kk * 4 + 3], wv.w, acc);
                }
                m = fmaxf(m, __fmul_rn((float)acc, sbsf2[o]));
                w[j] = acc;
            }
            orow[g] = make_uint4((unsigned)w[0], (unsigned)w[1],
                                 (unsigned)w[2], (unsigned)w[3]);
        }
    }
    warp_fmax_atomic(m, &g_hmax2);
}

// ---- K3b: sf2, cmb2, layer-3 bias quant -----------------------------------
__global__ void k3b_fin(const float* __restrict__ b3) {
    __shared__ float s_sf, s_inv;
    int t = threadIdx.x;  // 32 threads
    if (t == 0) {
        float sf = __fdiv_rn(fmaxf(__uint_as_float(g_hmax2), 1e-8f), 31.0f);
        g_sf2 = sf;
        s_sf = sf;
        s_inv = __fdiv_rn(1.0f, sf);
    }
    __syncthreads();
    g_cmb2[t] = __fmul_rn(g_bsf2[t], s_inv);
    {
        float bsf = __fmul_rn(g_wsc3[t], s_sf);
        g_bsf3[t] = bsf;
        g_bint3[t] = iclamp((int)rintf(__fdiv_rn(b3[t], bsf)), -32, 31);
    }
}

// ---- K4: acc2 -> q2 -> L3, store acc3 i16, scalar h-max -------------------
__global__ __launch_bounds__(256, 2) void k4_l3(int rows, int nt) {
    __shared__ int4 sW3[64];
    __shared__ int sb3[32];
    __shared__ float scmb2[32], sbsf2[32], sbsf3[32], scc[1];
    int t = threadIdx.x;
    if (t < 64) sW3[t] = ((const int4*)g_W3p)[t];
    if (t < 32) {
        scmb2[t] = g_cmb2[t];
        sbsf2[t] = g_bsf2[t];
        sb3[t] = g_bint3[t];
        sbsf3[t] = g_bsf3[t];
    }
    if (t == 0) scc[0] = g_sf2;
    __syncthreads();
    float sf2 = scc[0];
    float m = 0.f;

#pragma unroll 1
    for (int row = blockIdx.x * 256 + t; row < rows; row += nt) {
        const uint4* pa = g_a2 + (size_t)row * 8;
        int q2[8];
#pragma unroll
        for (int c = 0; c < 8; c++) {
            uint4 v = pa[c];
            int ob = c * 4;
            q2[c] = pack4i(
                fquant_pos((float)(int)v.x, scmb2[ob + 0], sbsf2[ob + 0], sf2),
                fquant_pos((float)(int)v.y, scmb2[ob + 1], sbsf2[ob + 1], sf2),
                fquant_pos((float)(int)v.z, scmb2[ob + 2], sbsf2[ob + 2], sf2),
                fquant_pos((float)(int)v.w, scmb2[ob + 3], sbsf2[ob + 3], sf2));
        }
        uint4* orow = g_a3 + (size_t)row * 4;
#pragma unroll
        for (int g = 0; g < 4; g++) {
            unsigned w[4];
#pragma unroll
            for (int j = 0; j < 4; j++) {
                int o0 = g * 8 + 2 * j, o1 = o0 + 1;
                int4 wa = sW3[o0 * 2], wb = sW3[o0 * 2 + 1];
                int4 wc = sW3[o1 * 2], wd = sW3[o1 * 2 + 1];
                int a0 = sb3[o0], a1 = sb3[o1];
                a0 = dp4a_(q2[0], wa.x, a0); a0 = dp4a_(q2[1], wa.y, a0);
                a0 = dp4a_(q2[2], wa.z, a0); a0 = dp4a_(q2[3], wa.w, a0);
                a0 = dp4a_(q2[4], wb.x, a0); a0 = dp4a_(q2[5], wb.y, a0);
                a0 = dp4a_(q2[6], wb.z, a0); a0 = dp4a_(q2[7], wb.w, a0);
                a1 = dp4a_(q2[0], wc.x, a1); a1 = dp4a_(q2[1], wc.y, a1);
                a1 = dp4a_(q2[2], wc.z, a1); a1 = dp4a_(q2[3], wc.w, a1);
                a1 = dp4a_(q2[4], wd.x, a1); a1 = dp4a_(q2[5], wd.y, a1);
                a1 = dp4a_(q2[6], wd.z, a1); a1 = dp4a_(q2[7], wd.w, a1);
                m = fmaxf(m, __fmul_rn((float)a0, sbsf3[o0]));
                m = fmaxf(m, __fmul_rn((float)a1, sbsf3[o1]));
                w[j] = ((unsigned)a0 & 0xFFFFu) | ((unsigned)a1 << 16);
            }
            orow[g] = make_uint4(w[0], w[1], w[2], w[3]);
        }
    }
    warp_fmax_atomic(m, &g_hmax3);
}

// ---- K4b: sf3, cmb3, layer-4 bias quant -----------------------------------
__global__ void k4b_fin(const float* __restrict__ b4) {
    __shared__ float s_sf, s_inv;
    int t = threadIdx.x;  // 32 threads
    if (t == 0) {
        float sf = __fdiv_rn(fmaxf(__uint_as_float(g_hmax3), 1e-8f), 31.0f);
        g_sf3 = sf;
        s_sf = sf;
        s_inv = __fdiv_rn(1.0f, sf);
    }
    __syncthreads();
    g_cmb3[t] = __fmul_rn(g_bsf3[t], s_inv);
    if (t < 5) {
        float bsf = __fmul_rn(g_wsc4[t], s_sf);
        g_bsf4[t] = bsf;
        g_bint4[t] = iclamp((int)rintf(__fdiv_rn(b4[t], bsf)), -32, 31);
    }
}

// ---- K5: acc3 -> q3 -> L4, softmax, store ---------------------------------
__global__ __launch_bounds__(256, 2) void k5_out(float* __restrict__ out,
                                                 int rows, int nt) {
    __shared__ int4 sW4[10];
    __shared__ int sb4[8];
    __shared__ float scmb3[32], sbsf3[32], sbsf4[8], scc[1];
    int t = threadIdx.x;
    if (t < 10) sW4[t] = ((const int4*)g_W4p)[t];
    if (t < 32) { scmb3[t] = g_cmb3[t]; sbsf3[t] = g_bsf3[t]; }
    if (t < 5) { sb4[t] = g_bint4[t]; sbsf4[t] = g_bsf4[t]; }
    if (t == 0) scc[0] = g_sf3;
    __syncthreads();
    float sf3 = scc[0];

#pragma unroll 1
    for (int row = blockIdx.x * 256 + t; row < rows; row += nt) {
        const uint4* pa = g_a3 + (size_t)row * 4;
        int q3[8];
#pragma unroll
        for (int c = 0; c < 4; c++) {
            uint4 v = pa[c];
            q3[c * 2 + 0] = quant4_i16(v.x, v.y, c * 8 + 0, scmb3, sbsf3, sf3);
            q3[c * 2 + 1] = quant4_i16(v.z, v.w, c * 8 + 4, scmb3, sbsf3, sf3);
        }
        float logit[5];
#pragma unroll
        for (int c = 0; c < 5; c++) {
            int4 wa = sW4[c * 2], wb = sW4[c * 2 + 1];
            int acc = sb4[c];
            acc = dp4a_(q3[0], wa.x, acc); acc = dp4a_(q3[1], wa.y, acc);
            acc = dp4a_(q3[2], wa.z, acc); acc = dp4a_(q3[3], wa.w, acc);
            acc = dp4a_(q3[4], wb.x, acc); acc = dp4a_(q3[5], wb.y, acc);
            acc = dp4a_(q3[6], wb.z, acc); acc = dp4a_(q3[7], wb.w, acc);
            logit[c] = __fmul_rn((float)acc, sbsf4[c]);
        }
        float mm = logit[0];
#pragma unroll
        for (int c = 1; c < 5; c++) mm = fmaxf(mm, logit[c]);
        float e[5], s = 0.f;
#pragma unroll
        for (int c = 0; c < 5; c++) { e[c] = __expf(logit[c] - mm); s += e[c]; }
        float rs = __frcp_rn(s);
        float* po = out + (size_t)row * 5;
#pragma unroll
        for (int c = 0; c < 5; c++) po[c] = e[c] * rs;
    }
}

// ---- launcher --------------------------------------------------------------
extern "C" void kernel_launch(void* const* d_in, const int* in_sizes, int n_in,
                              void* d_out, int out_size) {
    const float* x  = (const float*)d_in[0];
    const float* W1 = (const float*)d_in[1];
    const float* b1 = (const float*)d_in[2];
    const float* W2 = (const float*)d_in[3];
    const float* b2 = (const float*)d_in[4];
    const float* W3 = (const float*)d_in[5];
    const float* b3 = (const float*)d_in[6];
    const float* W4 = (const float*)d_in[7];
    const float* b4 = (const float*)d_in[8];
    float* out = (float*)d_out;

    int rows = in_sizes[0] / 16;
    if (rows > ROWS_CAP) rows = ROWS_CAP;

    int grid = (rows + 255) / 256;
    if (grid > 2368) grid = 2368;  // 148 SMs * 16 blocks
    int nt = grid * 256;

    k0_init<<<1, 256>>>(W1, W2, W3, W4);
    k1_absmax<<<1024, 256>>>(x, rows * 4);
    k1b_fin<<<1, 64>>>(b1);
    k2_l1<<<grid, 256>>>(x, rows, nt);
    k2b_fin<<<1, 64>>>(b2);
    k3_l2<<<grid, 256>>>(rows, nt);
    k3b_fin<<<1, 32>>>(b3);
    k4_l3<<<grid, 256>>>(rows, nt);
    k4b_fin<<<1, 32>>>(b4);
    k5_out<<<grid, 256>>>(out, rows, nt);
    (void)n_in; (void)out_size;
}